// round 1
// baseline (speedup 1.0000x reference)
#include <cuda_runtime.h>
#include <math.h>

#define BB   4
#define NN   4096
#define KK   32
#define HH   128

// scratch (static device arrays; no allocation)
__device__ float g_upd[BB * NN * HH];     // 8 MB
__device__ float g_mean[BB * HH];
__device__ float g_rstd[BB * HH];

__device__ __forceinline__ float gelu_exact(float x) {
    return 0.5f * x * (1.0f + erff(x * 0.70710678118654752440f));
}

// swizzled index into a [128][32] feature-major tile:
// row i holds the 32 edge values for feature i; 4-element groups XOR-swizzled
// so column writes are <=4-way conflicted and row reads are aligned float4.
__device__ __forceinline__ int sw_idx(int i, int e) {
    return i * KK + ((((e >> 2) ^ (i & 7)) << 2) | (e & 3));
}

__global__ __launch_bounds__(128)
void mpnn_msg_kernel(const float* __restrict__ atom_encode,
                     const float* __restrict__ atom_mask,
                     const float* __restrict__ dist,
                     const int*   __restrict__ edge_index,
                     const float* __restrict__ W0, const float* __restrict__ b0,
                     const float* __restrict__ W1, const float* __restrict__ b1,
                     const float* __restrict__ W2, const float* __restrict__ b2)
{
    __shared__ __align__(16) float Xs[HH * KK];   // 16 KB
    __shared__ __align__(16) float Hs[HH * KK];   // 16 KB
    __shared__ float selfs[HH];
    __shared__ float dists[KK];
    __shared__ float valids[KK];
    __shared__ float smask[KK];
    __shared__ int   idxs[KK];

    const int blk = blockIdx.x;
    const int b = blk >> 12;          // / NN
    const int n = blk & (NN - 1);
    const int t = threadIdx.x;

    const float m    = atom_mask[b * NN + n];
    const float encv = atom_encode[(b * NN + n) * HH + t];
    selfs[t] = encv * m;
    if (t < KK) {
        int ei = edge_index[(b * NN + n) * KK + t];
        valids[t] = (ei != -1) ? 1.0f : 0.0f;
        int ic = (ei < 0) ? 0 : ei;
        idxs[t]  = ic;
        smask[t] = atom_mask[b * NN + ic];
        dists[t] = dist[(b * NN + n) * KK + t];
    }
    __syncthreads();

    // ---- gather neighbor features (masked by neighbor mask) into Xs[i=t][e]
    #pragma unroll 4
    for (int e = 0; e < KK; e++) {
        float v = atom_encode[(b * NN + idxs[e]) * HH + t] * smask[e];
        Xs[sw_idx(t, e)] = v;
    }

    // ---- layer-0 self-half contribution: identical for all edges of this node
    float accS = b0[t];
    #pragma unroll 8
    for (int j = 0; j < HH; j++)
        accS = fmaf(selfs[j], W0[(HH + j) * HH + t], accS);
    const float w256 = W0[2 * HH * HH + t];

    float acc[KK];
    #pragma unroll
    for (int e = 0; e < KK; e++) acc[e] = fmaf(dists[e], w256, accS);

    __syncthreads();   // Xs ready

    // ---- layer-0 src-half: acc[e] += sum_i Xs[i][e] * W0[i][t]
    #pragma unroll 4
    for (int i = 0; i < HH; i++) {
        const float w = W0[i * HH + t];
        const float4* row = reinterpret_cast<const float4*>(&Xs[i * KK]);
        const int s = i & 7;
        #pragma unroll
        for (int g = 0; g < 8; g++) {
            float4 xv = row[g ^ s];
            acc[4*g+0] = fmaf(xv.x, w, acc[4*g+0]);
            acc[4*g+1] = fmaf(xv.y, w, acc[4*g+1]);
            acc[4*g+2] = fmaf(xv.z, w, acc[4*g+2]);
            acc[4*g+3] = fmaf(xv.w, w, acc[4*g+3]);
        }
    }

    // gelu -> Hs (h0)
    #pragma unroll
    for (int e = 0; e < KK; e++) Hs[sw_idx(t, e)] = gelu_exact(acc[e]);

    {
        const float bb = b1[t];
        #pragma unroll
        for (int e = 0; e < KK; e++) acc[e] = bb;
    }
    __syncthreads();   // Hs ready; everyone done with Xs

    // ---- layer-1
    #pragma unroll 4
    for (int j = 0; j < HH; j++) {
        const float w = W1[j * HH + t];
        const float4* row = reinterpret_cast<const float4*>(&Hs[j * KK]);
        const int s = j & 7;
        #pragma unroll
        for (int g = 0; g < 8; g++) {
            float4 xv = row[g ^ s];
            acc[4*g+0] = fmaf(xv.x, w, acc[4*g+0]);
            acc[4*g+1] = fmaf(xv.y, w, acc[4*g+1]);
            acc[4*g+2] = fmaf(xv.z, w, acc[4*g+2]);
            acc[4*g+3] = fmaf(xv.w, w, acc[4*g+3]);
        }
    }

    // gelu -> Xs (h1, reuse buffer)
    #pragma unroll
    for (int e = 0; e < KK; e++) Xs[sw_idx(t, e)] = gelu_exact(acc[e]);

    {
        const float bb = b2[t];
        #pragma unroll
        for (int e = 0; e < KK; e++) acc[e] = bb;
    }
    __syncthreads();   // Xs=h1 ready; everyone done with Hs

    // ---- layer-2
    #pragma unroll 4
    for (int j = 0; j < HH; j++) {
        const float w = W2[j * HH + t];
        const float4* row = reinterpret_cast<const float4*>(&Xs[j * KK]);
        const int s = j & 7;
        #pragma unroll
        for (int g = 0; g < 8; g++) {
            float4 xv = row[g ^ s];
            acc[4*g+0] = fmaf(xv.x, w, acc[4*g+0]);
            acc[4*g+1] = fmaf(xv.y, w, acc[4*g+1]);
            acc[4*g+2] = fmaf(xv.z, w, acc[4*g+2]);
            acc[4*g+3] = fmaf(xv.w, w, acc[4*g+3]);
        }
    }

    // ---- masked mean aggregation + residual + node mask
    float cnt = 0.0f, msum = 0.0f;
    #pragma unroll
    for (int e = 0; e < KK; e++) {
        cnt += valids[e];
        msum = fmaf(valids[e], gelu_exact(acc[e]), msum);
    }
    const float inv = 1.0f / fmaxf(cnt, 1.0f);
    g_upd[(b * NN + n) * HH + t] = (encv + msum * inv) * m;
}

__global__ __launch_bounds__(256)
void stats_kernel(const float* __restrict__ atom_mask)
{
    const int b = blockIdx.x >> 7;     // / HH
    const int h = blockIdx.x & (HH - 1);
    float s = 0.0f, sq = 0.0f, c = 0.0f;
    for (int n = threadIdx.x; n < NN; n += 256) {
        float v = g_upd[(b * NN + n) * HH + h];   // already masked
        s += v; sq += v * v;
        c += atom_mask[b * NN + n];
    }
    __shared__ float rs[256], rq[256], rc[256];
    rs[threadIdx.x] = s; rq[threadIdx.x] = sq; rc[threadIdx.x] = c;
    __syncthreads();
    for (int off = 128; off > 0; off >>= 1) {
        if (threadIdx.x < off) {
            rs[threadIdx.x] += rs[threadIdx.x + off];
            rq[threadIdx.x] += rq[threadIdx.x + off];
            rc[threadIdx.x] += rc[threadIdx.x + off];
        }
        __syncthreads();
    }
    if (threadIdx.x == 0) {
        float cnt = rc[0]; if (cnt == 0.0f) cnt = 1.0f;
        float mean = rs[0] / cnt;
        // sum over ALL n of (mf - mean)^2 = sq - 2*mean*s + NN*mean^2
        float var = (rq[0] - 2.0f * mean * rs[0] + (float)NN * mean * mean) / cnt;
        g_mean[b * HH + h] = mean;
        g_rstd[b * HH + h] = rsqrtf(var + 1e-5f);
    }
}

__global__ __launch_bounds__(256)
void norm_kernel(float* __restrict__ out,
                 const float* __restrict__ atom_mask,
                 const float* __restrict__ scale,
                 const float* __restrict__ shift)
{
    const int i = blockIdx.x * 256 + threadIdx.x;
    if (i >= BB * NN * HH) return;
    const int h  = i & (HH - 1);
    const int bn = i >> 7;
    const int b  = bn >> 12;
    const float v = g_upd[i];
    out[i] = ((v - g_mean[b * HH + h]) * g_rstd[b * HH + h] * scale[h] + shift[h])
             * atom_mask[bn];
}

__global__ __launch_bounds__(256)
void passthru_kernel(float* __restrict__ out,
                     const float* __restrict__ atom_mask,
                     const float* __restrict__ dist,
                     const int*   __restrict__ edge)
{
    const int M0 = BB * NN;            // 16384
    const int M1 = BB * NN * KK;       // 524288
    const int total = M0 + 2 * M1;
    const int i = blockIdx.x * 256 + threadIdx.x;
    if (i >= total) return;
    if (i < M0)            out[i] = atom_mask[i];
    else if (i < M0 + M1)  out[i] = dist[i - M0];
    else                   out[i] = (float)edge[i - M0 - M1];
}

extern "C" void kernel_launch(void* const* d_in, const int* in_sizes, int n_in,
                              void* d_out, int out_size)
{
    const float* atom_encode = (const float*)d_in[0];
    const float* atom_mask   = (const float*)d_in[1];
    const float* dist        = (const float*)d_in[2];
    const int*   edge_index  = (const int*)  d_in[3];
    const float* W0 = (const float*)d_in[4];
    const float* b0 = (const float*)d_in[5];
    const float* W1 = (const float*)d_in[6];
    const float* b1 = (const float*)d_in[7];
    const float* W2 = (const float*)d_in[8];
    const float* b2 = (const float*)d_in[9];
    const float* scale = (const float*)d_in[10];
    const float* shift = (const float*)d_in[11];
    float* out = (float*)d_out;

    mpnn_msg_kernel<<<BB * NN, 128>>>(atom_encode, atom_mask, dist, edge_index,
                                      W0, b0, W1, b1, W2, b2);
    stats_kernel<<<BB * HH, 256>>>(atom_mask);

    const int OUT0 = BB * NN * HH;                 // 2,097,152
    norm_kernel<<<(OUT0 + 255) / 256, 256>>>(out, atom_mask, scale, shift);

    const int PT = BB * NN + 2 * BB * NN * KK;     // 1,064,960
    if (out_size >= OUT0 + PT) {
        passthru_kernel<<<(PT + 255) / 256, 256>>>(out + OUT0, atom_mask, dist,
                                                   edge_index);
    }
}

// round 3
// speedup vs baseline: 2.1545x; 2.1545x over previous
#include <cuda_runtime.h>
#include <cuda_bf16.h>
#include <cstdint>
#include <math.h>

#define BB 4
#define NN 4096
#define KK 32
#define HH 128
#define NODES (BB*NN)

// ---------------- scratch (static, no allocation) ----------------
__device__ float g_upd[NODES * HH];          // 8 MB
__device__ float g_mean[BB * HH];
__device__ float g_rstd[BB * HH];
// prepped weights: [layer][quarter n32][plane hi/lo][n32 rows][256B swizzled]
__device__ __align__(16) unsigned char g_Wp[3 * 4 * 2 * 8192];

// ---------------- helpers ----------------
__device__ __forceinline__ uint32_t smem_u32(const void* p) {
    uint32_t a;
    asm("{ .reg .u64 t; cvta.to.shared.u64 t, %1; cvt.u32.u64 %0, t; }"
        : "=r"(a) : "l"(p));
    return a;
}
__device__ __forceinline__ float gelu_exact(float x) {
    return 0.5f * x * (1.0f + erff(x * 0.70710678118654752440f));
}
__device__ __forceinline__ void split2(float x, float y, uint32_t& hi, uint32_t& lo) {
    __nv_bfloat16 hx = __float2bfloat16(x);
    __nv_bfloat16 hy = __float2bfloat16(y);
    __nv_bfloat16 lx = __float2bfloat16(x - __bfloat162float(hx));
    __nv_bfloat16 ly = __float2bfloat16(y - __bfloat162float(hy));
    hi = (uint32_t)__bfloat16_as_ushort(hx) | ((uint32_t)__bfloat16_as_ushort(hy) << 16);
    lo = (uint32_t)__bfloat16_as_ushort(lx) | ((uint32_t)__bfloat16_as_ushort(ly) << 16);
}
__device__ __forceinline__ void ldm4(uint32_t* r, uint32_t addr) {
    asm volatile("ldmatrix.sync.aligned.m8n8.x4.shared.b16 {%0,%1,%2,%3}, [%4];"
        : "=r"(r[0]), "=r"(r[1]), "=r"(r[2]), "=r"(r[3]) : "r"(addr));
}
__device__ __forceinline__ void mma_bf16(float* c, const uint32_t* a, const uint32_t* b) {
    asm volatile(
        "mma.sync.aligned.m16n8k16.row.col.f32.bf16.bf16.f32 "
        "{%0,%1,%2,%3}, {%4,%5,%6,%7}, {%8,%9}, {%0,%1,%2,%3};"
        : "+f"(c[0]), "+f"(c[1]), "+f"(c[2]), "+f"(c[3])
        : "r"(a[0]), "r"(a[1]), "r"(a[2]), "r"(a[3]), "r"(b[0]), "r"(b[1]));
}

// ---------------- prep: W^T -> bf16 hi/lo, swizzled, quartered ----------------
__global__ void prep_weights(const float* __restrict__ W0,
                             const float* __restrict__ W1,
                             const float* __restrict__ W2)
{
    int i = blockIdx.x * blockDim.x + threadIdx.x;
    if (i >= 3 * HH * HH) return;
    int lyr = i >> 14, r = i & 16383, n = r >> 7, k = r & 127;
    const float* W = (lyr == 0) ? W0 : ((lyr == 1) ? W1 : W2);
    float v = W[k * HH + n];                    // layer0: rows 0..127 = src block
    __nv_bfloat16 h  = __float2bfloat16(v);
    __nv_bfloat16 lo = __float2bfloat16(v - __bfloat162float(h));
    int q = n >> 5, nl = n & 31;
    int byte = nl * 256 + (((k >> 3) ^ (nl & 7)) << 4) + ((k & 7) << 1);
    unsigned char* base = g_Wp + (size_t)((lyr * 4 + q) * 2) * 8192;
    *(__nv_bfloat16*)(base + byte)        = h;
    *(__nv_bfloat16*)(base + 8192 + byte) = lo;
}

// ---------------- main fused kernel ----------------
// smem layout (bytes)
#define OFF_AHI   0        // 32768 : A hi plane, 128 rows x 256B, chunk-swizzled
#define OFF_ALO   32768    // 32768 : A lo plane
#define OFF_B     65536    // 16384 : current weight quarter (hi 8K | lo 8K)
#define OFF_SELF  81920    // 2048  : masked self features [4][128]
#define OFF_SBIAS 83968    // 2048  : layer0 self-half bias [4][128]
#define OFF_MSUM  86016    // 2048  : per-node message sums [4][128]
#define OFF_W256  88064    // 512   : W0 dist row
#define OFF_BV    88576    // 1024  : b1,b2
#define OFF_DE    89600    // 512   : dist per edge
#define OFF_VLD   90112    // 512   : valid per edge
#define OFF_INV   90624    // 16
#define OFF_NM    90640    // 16
#define SMEM_BYTES 90656

__global__ __launch_bounds__(128)
void mpnn_tc(const float* __restrict__ enc, const float* __restrict__ mask,
             const float* __restrict__ dist, const int* __restrict__ eidx,
             const float* __restrict__ W0, const float* __restrict__ b0,
             const float* __restrict__ b1, const float* __restrict__ b2)
{
    extern __shared__ char smem[];
    uint32_t sb = smem_u32(smem);
    float* smf = (float*)smem;
    const int tid = threadIdx.x;
    const int w = tid >> 5, l = tid & 31;
    const int base_node = blockIdx.x << 2;
    const int batch = base_node >> 12;

    // ---- per-edge metadata (thread = edge row) ----
    const int ei = eidx[base_node * KK + tid];
    const float valid = (ei >= 0) ? 1.0f : 0.0f;
    const int gsrc = batch * NN + ((ei < 0) ? 0 : ei);
    const float smask = mask[gsrc];
    smf[(OFF_DE  >> 2) + tid] = dist[base_node * KK + tid];
    smf[(OFF_VLD >> 2) + tid] = valid;
    unsigned cnt = __reduce_add_sync(0xffffffffu, (ei >= 0) ? 1u : 0u);
    if (l == 0) smf[(OFF_INV >> 2) + w] = 1.0f / ((cnt == 0) ? 1.0f : (float)cnt);

    #pragma unroll
    for (int g = 0; g < 4; g++) {
        float mm = mask[base_node + g];
        smf[(OFF_SELF >> 2) + g * HH + tid] =
            enc[(size_t)(base_node + g) * HH + tid] * mm;
    }
    if (tid < 4) smf[(OFF_NM >> 2) + tid] = mask[base_node + tid];
    smf[(OFF_W256 >> 2) + tid]      = W0[256 * HH + tid];
    smf[(OFF_BV   >> 2) + tid]      = b1[tid];
    smf[(OFF_BV   >> 2) + HH + tid] = b2[tid];

    // ---- gather neighbor features -> A planes (bf16 hi/lo, swizzled) ----
    {
        const float4* rp = (const float4*)(enc + (size_t)gsrc * HH);
        const int row = tid, rp7 = row & 7;
        #pragma unroll
        for (int c = 0; c < 16; c++) {
            float4 v0 = rp[2 * c], v1 = rp[2 * c + 1];
            uint32_t h0, l0, h1, l1, h2, l2, h3, l3;
            split2(v0.x * smask, v0.y * smask, h0, l0);
            split2(v0.z * smask, v0.w * smask, h1, l1);
            split2(v1.x * smask, v1.y * smask, h2, l2);
            split2(v1.z * smask, v1.w * smask, h3, l3);
            uint32_t off = (uint32_t)row * 256 + (uint32_t)((c ^ rp7) << 4);
            *(uint4*)(smem + OFF_AHI + off) = make_uint4(h0, h1, h2, h3);
            *(uint4*)(smem + OFF_ALO + off) = make_uint4(l0, l1, l2, l3);
        }
    }
    __syncthreads();   // SELF/DE/VLD visible

    // ---- layer-0 self-half bias (per node, per out-col=tid) ----
    {
        float s0 = b0[tid], s1 = s0, s2 = s0, s3 = s0;
        const float* sp = &smf[OFF_SELF >> 2];
        #pragma unroll 4
        for (int j = 0; j < HH; j++) {
            float ww = W0[(HH + j) * HH + tid];
            s0 = fmaf(sp[j],          ww, s0);
            s1 = fmaf(sp[HH + j],     ww, s1);
            s2 = fmaf(sp[2 * HH + j], ww, s2);
            s3 = fmaf(sp[3 * HH + j], ww, s3);
        }
        smf[(OFF_SBIAS >> 2) + 0 * HH + tid] = s0;
        smf[(OFF_SBIAS >> 2) + 1 * HH + tid] = s1;
        smf[(OFF_SBIAS >> 2) + 2 * HH + tid] = s2;
        smf[(OFF_SBIAS >> 2) + 3 * HH + tid] = s3;
    }

    // ---- lane constants for ldmatrix addressing ----
    const int rA0 = (w << 5) + (l & 15), rA1 = rA0 + 16;
    const uint32_t cselA = (uint32_t)(l >> 4);
    const uint32_t baseA0 = sb + OFF_AHI + (uint32_t)rA0 * 256;
    const uint32_t baseA1 = sb + OFF_AHI + (uint32_t)rA1 * 256;
    const uint32_t parA0 = (uint32_t)(rA0 & 7), parA1 = (uint32_t)(rA1 & 7);
    const int rB = (l & 7) + ((l >> 4) << 3);
    const uint32_t cselB = (uint32_t)((l >> 3) & 1);
    const uint32_t baseB = sb + OFF_B + (uint32_t)rB * 256;
    const uint32_t parB = (uint32_t)(rB & 7);

    float de4[4], vl4[4];
    #pragma unroll
    for (int ri = 0; ri < 4; ri++) {
        int rr = (w << 5) + (l >> 2) + 8 * ri;
        de4[ri] = smf[(OFF_DE  >> 2) + rr];
        vl4[ri] = smf[(OFF_VLD >> 2) + rr];
    }
    __syncthreads();   // SBIAS + A planes visible

    float acc[2][16][4];
    const int c2 = (l & 3) << 1;

    #pragma unroll 1
    for (int layer = 0; layer < 3; layer++) {
        // ---- init acc with bias ----
        if (layer == 0) {
            #pragma unroll
            for (int nt = 0; nt < 16; nt++) {
                float2 sb2 = *(float2*)&smf[(OFF_SBIAS >> 2) + w * HH + 8 * nt + c2];
                float2 w2  = *(float2*)&smf[(OFF_W256  >> 2) + 8 * nt + c2];
                #pragma unroll
                for (int m = 0; m < 2; m++) {
                    acc[m][nt][0] = fmaf(de4[2 * m],     w2.x, sb2.x);
                    acc[m][nt][1] = fmaf(de4[2 * m],     w2.y, sb2.y);
                    acc[m][nt][2] = fmaf(de4[2 * m + 1], w2.x, sb2.x);
                    acc[m][nt][3] = fmaf(de4[2 * m + 1], w2.y, sb2.y);
                }
            }
        } else {
            const float* bv = &smf[(OFF_BV >> 2) + (layer - 1) * HH];
            #pragma unroll
            for (int nt = 0; nt < 16; nt++) {
                float2 b2v = *(float2*)&bv[8 * nt + c2];
                #pragma unroll
                for (int m = 0; m < 2; m++) {
                    acc[m][nt][0] = b2v.x; acc[m][nt][1] = b2v.y;
                    acc[m][nt][2] = b2v.x; acc[m][nt][3] = b2v.y;
                }
            }
        }

        // ---- 4 weight quarters: stage 16KB, then 8 k-steps of mma ----
        const unsigned char* wsrc = g_Wp + (size_t)layer * 65536;
        #pragma unroll
        for (int q = 0; q < 4; q++) {
            __syncthreads();   // previous consumers of B done
            {
                const uint4* src = (const uint4*)(wsrc + q * 16384);
                uint4* dst = (uint4*)(smem + OFF_B);
                #pragma unroll
                for (int i = 0; i < 8; i++) dst[tid + 128 * i] = src[tid + 128 * i];
            }
            __syncthreads();   // B visible

            #pragma unroll
            for (int ks = 0; ks < 8; ks++) {
                uint32_t ah0[4], ah1[4], al0[4], al1[4], bhh[2][4], bll[2][4];
                const uint32_t kA = (uint32_t)(2 * ks) + cselA;
                const uint32_t kB = (uint32_t)(2 * ks) + cselB;
                ldm4(ah0, baseA0 + ((kA ^ parA0) << 4));
                ldm4(ah1, baseA1 + ((kA ^ parA1) << 4));
                ldm4(al0, baseA0 + 32768 + ((kA ^ parA0) << 4));
                ldm4(al1, baseA1 + 32768 + ((kA ^ parA1) << 4));
                #pragma unroll
                for (int jj = 0; jj < 2; jj++) {
                    ldm4(bhh[jj], baseB + jj * 4096 + ((kB ^ parB) << 4));
                    ldm4(bll[jj], baseB + 8192 + jj * 4096 + ((kB ^ parB) << 4));
                }
                #pragma unroll
                for (int tt = 0; tt < 4; tt++) {
                    const int nt = 4 * q + tt;
                    const uint32_t* bH = &bhh[tt >> 1][(tt & 1) << 1];
                    const uint32_t* bL = &bll[tt >> 1][(tt & 1) << 1];
                    mma_bf16(acc[0][nt], ah0, bH);
                    mma_bf16(acc[1][nt], ah1, bH);
                    mma_bf16(acc[0][nt], al0, bH);
                    mma_bf16(acc[1][nt], al1, bH);
                    mma_bf16(acc[0][nt], ah0, bL);
                    mma_bf16(acc[1][nt], ah1, bL);
                }
            }
        }
        __syncthreads();   // all mma done before A overwrite / final reduce

        if (layer < 2) {
            // ---- epilogue: gelu -> next A planes (bf16 hi/lo, swizzled) ----
            const int r0 = (w << 5) + (l >> 2);
            #pragma unroll
            for (int m = 0; m < 2; m++) {
                const int ra = r0 + 16 * m, rb = ra + 8;
                const uint32_t sa = (uint32_t)ra * 256 + (uint32_t)(c2 << 1);
                const uint32_t sbt = (uint32_t)rb * 256 + (uint32_t)(c2 << 1);
                #pragma unroll
                for (int nt = 0; nt < 16; nt++) {
                    float v0 = gelu_exact(acc[m][nt][0]);
                    float v1 = gelu_exact(acc[m][nt][1]);
                    float v2 = gelu_exact(acc[m][nt][2]);
                    float v3 = gelu_exact(acc[m][nt][3]);
                    uint32_t hA, lA, hB, lB;
                    split2(v0, v1, hA, lA);
                    split2(v2, v3, hB, lB);
                    uint32_t oa = sa  + (uint32_t)((nt ^ (ra & 7)) << 4);
                    uint32_t ob = sbt + (uint32_t)((nt ^ (rb & 7)) << 4);
                    *(uint32_t*)(smem + OFF_AHI + oa) = hA;
                    *(uint32_t*)(smem + OFF_ALO + oa) = lA;
                    *(uint32_t*)(smem + OFF_AHI + ob) = hB;
                    *(uint32_t*)(smem + OFF_ALO + ob) = lB;
                }
            }
            __syncthreads();
        } else {
            // ---- final: gelu*valid, reduce 32 edges -> per-node msum ----
            #pragma unroll
            for (int nt = 0; nt < 16; nt++) {
                float s0 = gelu_exact(acc[0][nt][0]) * vl4[0]
                         + gelu_exact(acc[0][nt][2]) * vl4[1]
                         + gelu_exact(acc[1][nt][0]) * vl4[2]
                         + gelu_exact(acc[1][nt][2]) * vl4[3];
                float s1 = gelu_exact(acc[0][nt][1]) * vl4[0]
                         + gelu_exact(acc[0][nt][3]) * vl4[1]
                         + gelu_exact(acc[1][nt][1]) * vl4[2]
                         + gelu_exact(acc[1][nt][3]) * vl4[3];
                #pragma unroll
                for (int sh = 4; sh < 32; sh <<= 1) {
                    s0 += __shfl_xor_sync(0xffffffffu, s0, sh);
                    s1 += __shfl_xor_sync(0xffffffffu, s1, sh);
                }
                if (l < 4) {
                    smf[(OFF_MSUM >> 2) + w * HH + 8 * nt + c2]     = s0;
                    smf[(OFF_MSUM >> 2) + w * HH + 8 * nt + c2 + 1] = s1;
                }
            }
            __syncthreads();
            #pragma unroll
            for (int g = 0; g < 4; g++) {
                float ms  = smf[(OFF_MSUM >> 2) + g * HH + tid];
                float upd = smf[(OFF_SELF >> 2) + g * HH + tid]
                          + ms * smf[(OFF_INV >> 2) + g] * smf[(OFF_NM >> 2) + g];
                g_upd[(size_t)(base_node + g) * HH + tid] = upd;
            }
        }
    }
}

// ---------------- graph norm + output assembly ----------------
__global__ __launch_bounds__(256)
void stats_kernel(const float* __restrict__ atom_mask)
{
    const int b = blockIdx.x >> 7;
    const int h = blockIdx.x & (HH - 1);
    float s = 0.0f, sq = 0.0f, c = 0.0f;
    for (int n = threadIdx.x; n < NN; n += 256) {
        float v = g_upd[((size_t)b * NN + n) * HH + h];
        s += v; sq += v * v;
        c += atom_mask[b * NN + n];
    }
    __shared__ float rs[256], rq[256], rc[256];
    rs[threadIdx.x] = s; rq[threadIdx.x] = sq; rc[threadIdx.x] = c;
    __syncthreads();
    for (int off = 128; off > 0; off >>= 1) {
        if (threadIdx.x < off) {
            rs[threadIdx.x] += rs[threadIdx.x + off];
            rq[threadIdx.x] += rq[threadIdx.x + off];
            rc[threadIdx.x] += rc[threadIdx.x + off];
        }
        __syncthreads();
    }
    if (threadIdx.x == 0) {
        float cnt = rc[0]; if (cnt == 0.0f) cnt = 1.0f;
        float mean = rs[0] / cnt;
        float var = (rq[0] - 2.0f * mean * rs[0] + (float)NN * mean * mean) / cnt;
        g_mean[b * HH + h] = mean;
        g_rstd[b * HH + h] = rsqrtf(var + 1e-5f);
    }
}

__global__ __launch_bounds__(256)
void norm_kernel(float* __restrict__ out,
                 const float* __restrict__ atom_mask,
                 const float* __restrict__ scale,
                 const float* __restrict__ shift)
{
    const int i = blockIdx.x * 256 + threadIdx.x;
    if (i >= NODES * HH) return;
    const int h  = i & (HH - 1);
    const int bn = i >> 7;
    const int b  = bn >> 12;
    const float v = g_upd[i];
    out[i] = ((v - g_mean[b * HH + h]) * g_rstd[b * HH + h] * scale[h] + shift[h])
             * atom_mask[bn];
}

__global__ __launch_bounds__(256)
void passthru_kernel(float* __restrict__ out,
                     const float* __restrict__ atom_mask,
                     const float* __restrict__ dist,
                     const int*   __restrict__ edge)
{
    const int M0 = NODES;
    const int M1 = NODES * KK;
    const int total = M0 + 2 * M1;
    const int i = blockIdx.x * 256 + threadIdx.x;
    if (i >= total) return;
    if (i < M0)            out[i] = atom_mask[i];
    else if (i < M0 + M1)  out[i] = dist[i - M0];
    else                   out[i] = (float)edge[i - M0 - M1];
}

extern "C" void kernel_launch(void* const* d_in, const int* in_sizes, int n_in,
                              void* d_out, int out_size)
{
    const float* atom_encode = (const float*)d_in[0];
    const float* atom_mask   = (const float*)d_in[1];
    const float* dist        = (const float*)d_in[2];
    const int*   edge_index  = (const int*)  d_in[3];
    const float* W0 = (const float*)d_in[4];
    const float* b0 = (const float*)d_in[5];
    const float* b1 = (const float*)d_in[7];
    const float* b2 = (const float*)d_in[9];
    const float* scale = (const float*)d_in[10];
    const float* shift = (const float*)d_in[11];
    float* out = (float*)d_out;

    cudaFuncSetAttribute(mpnn_tc, cudaFuncAttributeMaxDynamicSharedMemorySize,
                         SMEM_BYTES);

    prep_weights<<<(3 * HH * HH + 255) / 256, 256>>>(
        (const float*)d_in[4], (const float*)d_in[6], (const float*)d_in[8]);
    mpnn_tc<<<NODES / 4, 128, SMEM_BYTES>>>(atom_encode, atom_mask, dist,
                                            edge_index, W0, b0, b1, b2);
    stats_kernel<<<BB * HH, 256>>>(atom_mask);

    const int OUT0 = NODES * HH;
    norm_kernel<<<(OUT0 + 255) / 256, 256>>>(out, atom_mask, scale, shift);

    const int PT = NODES + 2 * NODES * KK;
    if (out_size >= OUT0 + PT) {
        passthru_kernel<<<(PT + 255) / 256, 256>>>(out + OUT0, atom_mask, dist,
                                                   edge_index);
    }
}

// round 4
// speedup vs baseline: 2.4797x; 1.1509x over previous
#include <cuda_runtime.h>
#include <cuda_bf16.h>
#include <cstdint>
#include <math.h>

#define BB 4
#define NN 4096
#define KK 32
#define HH 128
#define NODES (BB*NN)

// ---------------- scratch (static, no allocation) ----------------
__device__ float g_upd[NODES * HH];          // 8 MB
__device__ float g_sbias[NODES * HH];        // 8 MB: b0 + self@W0_self per node
__device__ float g_mean[BB * HH];
__device__ float g_rstd[BB * HH];
// prepped weights: slots 0..2 = W0_src,W1,W2; slot 3 = W0_self.
// per slot: 4 quarters x (hi 8192 B | lo 8192 B), swizzled.
__device__ __align__(16) unsigned char g_Wp[4 * 65536];

// ---------------- helpers ----------------
__device__ __forceinline__ uint32_t smem_u32(const void* p) {
    uint32_t a;
    asm("{ .reg .u64 t; cvta.to.shared.u64 t, %1; cvt.u32.u64 %0, t; }"
        : "=r"(a) : "l"(p));
    return a;
}
__device__ __forceinline__ float gelu_exact(float x) {
    return 0.5f * x * (1.0f + erff(x * 0.70710678118654752440f));
}
__device__ __forceinline__ void split2(float x, float y, uint32_t& hi, uint32_t& lo) {
    __nv_bfloat16 hx = __float2bfloat16(x);
    __nv_bfloat16 hy = __float2bfloat16(y);
    __nv_bfloat16 lx = __float2bfloat16(x - __bfloat162float(hx));
    __nv_bfloat16 ly = __float2bfloat16(y - __bfloat162float(hy));
    hi = (uint32_t)__bfloat16_as_ushort(hx) | ((uint32_t)__bfloat16_as_ushort(hy) << 16);
    lo = (uint32_t)__bfloat16_as_ushort(lx) | ((uint32_t)__bfloat16_as_ushort(ly) << 16);
}
__device__ __forceinline__ void ldm4(uint32_t* r, uint32_t addr) {
    asm volatile("ldmatrix.sync.aligned.m8n8.x4.shared.b16 {%0,%1,%2,%3}, [%4];"
        : "=r"(r[0]), "=r"(r[1]), "=r"(r[2]), "=r"(r[3]) : "r"(addr));
}
__device__ __forceinline__ void mma_bf16(float* c, const uint32_t* a, const uint32_t* b) {
    asm volatile(
        "mma.sync.aligned.m16n8k16.row.col.f32.bf16.bf16.f32 "
        "{%0,%1,%2,%3}, {%4,%5,%6,%7}, {%8,%9}, {%0,%1,%2,%3};"
        : "+f"(c[0]), "+f"(c[1]), "+f"(c[2]), "+f"(c[3])
        : "r"(a[0]), "r"(a[1]), "r"(a[2]), "r"(a[3]), "r"(b[0]), "r"(b[1]));
}
#define CP_ASYNC16(dst, src) \
    asm volatile("cp.async.cg.shared.global [%0], [%1], 16;" \
        :: "r"(dst), "l"(src) : "memory")
#define CP_COMMIT() asm volatile("cp.async.commit_group;" ::: "memory")
#define CP_WAIT1()  asm volatile("cp.async.wait_group 1;" ::: "memory")
#define CP_WAIT0()  asm volatile("cp.async.wait_group 0;" ::: "memory")

// ---------------- prep: W -> bf16 hi/lo, swizzled, quartered ----------------
__global__ void prep_weights(const float* __restrict__ W0,
                             const float* __restrict__ W1,
                             const float* __restrict__ W2)
{
    int i = blockIdx.x * blockDim.x + threadIdx.x;
    if (i >= 4 * HH * HH) return;
    int lyr = i >> 14, r = i & 16383, n = r >> 7, k = r & 127;
    float v;
    if (lyr == 0)      v = W0[k * HH + n];            // src block rows 0..127
    else if (lyr == 1) v = W1[k * HH + n];
    else if (lyr == 2) v = W2[k * HH + n];
    else               v = W0[(HH + k) * HH + n];     // self block rows 128..255
    __nv_bfloat16 h  = __float2bfloat16(v);
    __nv_bfloat16 lo = __float2bfloat16(v - __bfloat162float(h));
    int q = n >> 5, nl = n & 31;
    int byte = nl * 256 + (((k >> 3) ^ (nl & 7)) << 4) + ((k & 7) << 1);
    unsigned char* base = g_Wp + (size_t)((lyr * 4 + q) * 2) * 8192;
    *(__nv_bfloat16*)(base + byte)        = h;
    *(__nv_bfloat16*)(base + 8192 + byte) = lo;
}

// ---------------- self-bias mini-GEMM: g_sbias = b0 + self@W0_self ----------------
// CTA = 128 nodes; A planes 64 KB + full-layer B 64 KB; 128 CTAs, one wave.
#define SB_SMEM 131072
__global__ __launch_bounds__(128)
void sbias_kernel(const float* __restrict__ enc, const float* __restrict__ mask,
                  const float* __restrict__ b0)
{
    extern __shared__ char smem[];
    uint32_t sb = smem_u32(smem);
    const int tid = threadIdx.x;
    const int w = tid >> 5, l = tid & 31;
    const int base_node = blockIdx.x << 7;

    // gather masked self rows into A planes (hi @0, lo @32768)
    {
        const int node = base_node + tid;
        const float mm = mask[node];
        const float4* rp = (const float4*)(enc + (size_t)node * HH);
        const int rp7 = tid & 7;
        #pragma unroll
        for (int c = 0; c < 16; c++) {
            float4 v0 = rp[2 * c], v1 = rp[2 * c + 1];
            uint32_t h0, l0, h1, l1, h2, l2, h3, l3;
            split2(v0.x * mm, v0.y * mm, h0, l0);
            split2(v0.z * mm, v0.w * mm, h1, l1);
            split2(v1.x * mm, v1.y * mm, h2, l2);
            split2(v1.z * mm, v1.w * mm, h3, l3);
            uint32_t off = (uint32_t)tid * 256 + (uint32_t)((c ^ rp7) << 4);
            *(uint4*)(smem + off)         = make_uint4(h0, h1, h2, h3);
            *(uint4*)(smem + 32768 + off) = make_uint4(l0, l1, l2, l3);
        }
    }
    // stage full W0_self (slot 3): 64 KB
    {
        const uint4* src = (const uint4*)(g_Wp + 3 * 65536);
        uint4* dst = (uint4*)(smem + 65536);
        #pragma unroll
        for (int i = 0; i < 32; i++) dst[tid + 128 * i] = src[tid + 128 * i];
    }
    __syncthreads();

    const int rA0 = (w << 5) + (l & 15), rA1 = rA0 + 16;
    const uint32_t cselA = (uint32_t)(l >> 4);
    const uint32_t baseA0 = sb + (uint32_t)rA0 * 256;
    const uint32_t baseA1 = sb + (uint32_t)rA1 * 256;
    const uint32_t parA0 = (uint32_t)(rA0 & 7), parA1 = (uint32_t)(rA1 & 7);
    const int rB = (l & 7) + ((l >> 4) << 3);
    const uint32_t cselB = (uint32_t)((l >> 3) & 1);
    const uint32_t parB = (uint32_t)(rB & 7);
    const int c2 = (l & 3) << 1;

    float acc[2][16][4];
    #pragma unroll
    for (int nt = 0; nt < 16; nt++) {
        float bx = b0[8 * nt + c2], by = b0[8 * nt + c2 + 1];
        #pragma unroll
        for (int m = 0; m < 2; m++) {
            acc[m][nt][0] = bx; acc[m][nt][1] = by;
            acc[m][nt][2] = bx; acc[m][nt][3] = by;
        }
    }

    #pragma unroll
    for (int q = 0; q < 4; q++) {
        const uint32_t baseBq = sb + 65536 + (uint32_t)q * 16384 + (uint32_t)rB * 256;
        #pragma unroll
        for (int ks = 0; ks < 8; ks++) {
            uint32_t ah0[4], ah1[4], al0[4], al1[4], bhh[2][4], bll[2][4];
            const uint32_t kA = (uint32_t)(2 * ks) + cselA;
            const uint32_t kB = (uint32_t)(2 * ks) + cselB;
            ldm4(ah0, baseA0 + ((kA ^ parA0) << 4));
            ldm4(ah1, baseA1 + ((kA ^ parA1) << 4));
            ldm4(al0, baseA0 + 32768 + ((kA ^ parA0) << 4));
            ldm4(al1, baseA1 + 32768 + ((kA ^ parA1) << 4));
            #pragma unroll
            for (int jj = 0; jj < 2; jj++) {
                ldm4(bhh[jj], baseBq + jj * 4096 + ((kB ^ parB) << 4));
                ldm4(bll[jj], baseBq + 8192 + jj * 4096 + ((kB ^ parB) << 4));
            }
            #pragma unroll
            for (int tt = 0; tt < 4; tt++) {
                const int nt = 4 * q + tt;
                const uint32_t* bH = &bhh[tt >> 1][(tt & 1) << 1];
                const uint32_t* bL = &bll[tt >> 1][(tt & 1) << 1];
                mma_bf16(acc[0][nt], ah0, bH);
                mma_bf16(acc[1][nt], ah1, bH);
                mma_bf16(acc[0][nt], al0, bH);
                mma_bf16(acc[1][nt], al1, bH);
                mma_bf16(acc[0][nt], ah0, bL);
                mma_bf16(acc[1][nt], ah1, bL);
            }
        }
    }

    #pragma unroll
    for (int m = 0; m < 2; m++) {
        const int row0 = base_node + (w << 5) + (m << 4) + (l >> 2);
        #pragma unroll
        for (int nt = 0; nt < 16; nt++) {
            *(float2*)&g_sbias[(size_t)row0 * HH + 8 * nt + c2] =
                make_float2(acc[m][nt][0], acc[m][nt][1]);
            *(float2*)&g_sbias[(size_t)(row0 + 8) * HH + 8 * nt + c2] =
                make_float2(acc[m][nt][2], acc[m][nt][3]);
        }
    }
}

// ---------------- main fused kernel ----------------
// smem layout (bytes)
#define OFF_AHI   0        // 32768 : A hi plane, 128 rows x 256B, chunk-swizzled
#define OFF_ALO   32768    // 32768 : A lo plane
#define OFF_B     65536    // 32768 : double-buffered weight quarter (2 x 16 KB)
#define OFF_SELF  98304    // 2048
#define OFF_SBIAS 100352   // 2048
#define OFF_MSUM  102400   // 2048
#define OFF_W256  104448   // 512
#define OFF_BV    104960   // 1024
#define OFF_DE    105984   // 512
#define OFF_VLD   106496   // 512
#define OFF_INV   107008   // 16
#define OFF_NM    107024   // 16
#define SMEM_BYTES 107040

__global__ __launch_bounds__(128)
void mpnn_tc(const float* __restrict__ enc, const float* __restrict__ mask,
             const float* __restrict__ dist, const int* __restrict__ eidx,
             const float* __restrict__ W0,
             const float* __restrict__ b1, const float* __restrict__ b2)
{
    extern __shared__ char smem[];
    uint32_t sb = smem_u32(smem);
    float* smf = (float*)smem;
    const int tid = threadIdx.x;
    const int w = tid >> 5, l = tid & 31;
    const int base_node = blockIdx.x << 2;
    const int batch = base_node >> 12;

    // prologue: prefetch weight stage 0 immediately
    {
        const char* src = (const char*)g_Wp + tid * 16;
        uint32_t dst = sb + OFF_B + tid * 16;
        #pragma unroll
        for (int i = 0; i < 8; i++)
            CP_ASYNC16(dst + i * 2048, src + i * 2048);
        CP_COMMIT();
    }

    // ---- per-edge metadata (thread = edge row) ----
    const int ei = eidx[base_node * KK + tid];
    const float valid = (ei >= 0) ? 1.0f : 0.0f;
    const int gsrc = batch * NN + ((ei < 0) ? 0 : ei);
    const float smask = mask[gsrc];
    smf[(OFF_DE  >> 2) + tid] = dist[base_node * KK + tid];
    smf[(OFF_VLD >> 2) + tid] = valid;
    unsigned cnt = __reduce_add_sync(0xffffffffu, (ei >= 0) ? 1u : 0u);
    if (l == 0) smf[(OFF_INV >> 2) + w] = 1.0f / ((cnt == 0) ? 1.0f : (float)cnt);

    #pragma unroll
    for (int g = 0; g < 4; g++) {
        float mm = mask[base_node + g];
        smf[(OFF_SELF  >> 2) + g * HH + tid] =
            enc[(size_t)(base_node + g) * HH + tid] * mm;
        smf[(OFF_SBIAS >> 2) + g * HH + tid] =
            g_sbias[(size_t)(base_node + g) * HH + tid];
    }
    if (tid < 4) smf[(OFF_NM >> 2) + tid] = mask[base_node + tid];
    smf[(OFF_W256 >> 2) + tid]      = W0[256 * HH + tid];
    smf[(OFF_BV   >> 2) + tid]      = b1[tid];
    smf[(OFF_BV   >> 2) + HH + tid] = b2[tid];

    // ---- gather neighbor features -> A planes (bf16 hi/lo, swizzled) ----
    {
        const float4* rp = (const float4*)(enc + (size_t)gsrc * HH);
        const int rp7 = tid & 7;
        #pragma unroll
        for (int c = 0; c < 16; c++) {
            float4 v0 = rp[2 * c], v1 = rp[2 * c + 1];
            uint32_t h0, l0, h1, l1, h2, l2, h3, l3;
            split2(v0.x * smask, v0.y * smask, h0, l0);
            split2(v0.z * smask, v0.w * smask, h1, l1);
            split2(v1.x * smask, v1.y * smask, h2, l2);
            split2(v1.z * smask, v1.w * smask, h3, l3);
            uint32_t off = (uint32_t)tid * 256 + (uint32_t)((c ^ rp7) << 4);
            *(uint4*)(smem + OFF_AHI + off) = make_uint4(h0, h1, h2, h3);
            *(uint4*)(smem + OFF_ALO + off) = make_uint4(l0, l1, l2, l3);
        }
    }

    // ---- lane constants for ldmatrix addressing ----
    const int rA0 = (w << 5) + (l & 15), rA1 = rA0 + 16;
    const uint32_t cselA = (uint32_t)(l >> 4);
    const uint32_t baseA0 = sb + OFF_AHI + (uint32_t)rA0 * 256;
    const uint32_t baseA1 = sb + OFF_AHI + (uint32_t)rA1 * 256;
    const uint32_t parA0 = (uint32_t)(rA0 & 7), parA1 = (uint32_t)(rA1 & 7);
    const int rB = (l & 7) + ((l >> 4) << 3);
    const uint32_t cselB = (uint32_t)((l >> 3) & 1);
    const uint32_t parB = (uint32_t)(rB & 7);
    const int c2 = (l & 3) << 1;

    float de4[4], vl4[4];
    #pragma unroll
    for (int ri = 0; ri < 4; ri++) {
        int rr = (w << 5) + (l >> 2) + 8 * ri;
        de4[ri] = smf[(OFF_DE  >> 2) + rr];
        vl4[ri] = smf[(OFF_VLD >> 2) + rr];
    }
    __syncthreads();   // A planes + SBIAS/SELF/DE/VLD visible

    float acc[2][16][4];
    int s = 0;   // global weight stage 0..11

    #pragma unroll 1
    for (int layer = 0; layer < 3; layer++) {
        // ---- init acc with bias ----
        if (layer == 0) {
            #pragma unroll
            for (int nt = 0; nt < 16; nt++) {
                float2 sb2 = *(float2*)&smf[(OFF_SBIAS >> 2) + w * HH + 8 * nt + c2];
                float2 w2  = *(float2*)&smf[(OFF_W256  >> 2) + 8 * nt + c2];
                #pragma unroll
                for (int m = 0; m < 2; m++) {
                    acc[m][nt][0] = fmaf(de4[2 * m],     w2.x, sb2.x);
                    acc[m][nt][1] = fmaf(de4[2 * m],     w2.y, sb2.y);
                    acc[m][nt][2] = fmaf(de4[2 * m + 1], w2.x, sb2.x);
                    acc[m][nt][3] = fmaf(de4[2 * m + 1], w2.y, sb2.y);
                }
            }
        } else {
            const float* bv = &smf[(OFF_BV >> 2) + (layer - 1) * HH];
            #pragma unroll
            for (int nt = 0; nt < 16; nt++) {
                float2 b2v = *(float2*)&bv[8 * nt + c2];
                #pragma unroll
                for (int m = 0; m < 2; m++) {
                    acc[m][nt][0] = b2v.x; acc[m][nt][1] = b2v.y;
                    acc[m][nt][2] = b2v.x; acc[m][nt][3] = b2v.y;
                }
            }
        }

        // ---- 4 weight quarters; double-buffered cp.async pipeline ----
        #pragma unroll
        for (int q = 0; q < 4; q++) {
            // prefetch next stage (buffer last consumed 2 stages ago; the
            // end-of-iteration barrier of stage s-1 guarantees it is free)
            if (s + 1 < 12) {
                const char* src = (const char*)g_Wp + (s + 1) * 16384 + tid * 16;
                uint32_t dst = sb + OFF_B + ((s + 1) & 1) * 16384 + tid * 16;
                #pragma unroll
                for (int i = 0; i < 8; i++)
                    CP_ASYNC16(dst + i * 2048, src + i * 2048);
                CP_COMMIT();
                CP_WAIT1();
            } else {
                CP_WAIT0();
            }
            __syncthreads();   // stage s data visible to all warps

            const uint32_t baseB = sb + OFF_B + (uint32_t)((s & 1) * 16384)
                                 + (uint32_t)rB * 256;
            #pragma unroll
            for (int ks = 0; ks < 8; ks++) {
                uint32_t ah0[4], ah1[4], al0[4], al1[4], bhh[2][4], bll[2][4];
                const uint32_t kA = (uint32_t)(2 * ks) + cselA;
                const uint32_t kB = (uint32_t)(2 * ks) + cselB;
                ldm4(ah0, baseA0 + ((kA ^ parA0) << 4));
                ldm4(ah1, baseA1 + ((kA ^ parA1) << 4));
                ldm4(al0, baseA0 + 32768 + ((kA ^ parA0) << 4));
                ldm4(al1, baseA1 + 32768 + ((kA ^ parA1) << 4));
                #pragma unroll
                for (int jj = 0; jj < 2; jj++) {
                    ldm4(bhh[jj], baseB + jj * 4096 + ((kB ^ parB) << 4));
                    ldm4(bll[jj], baseB + 8192 + jj * 4096 + ((kB ^ parB) << 4));
                }
                #pragma unroll
                for (int tt = 0; tt < 4; tt++) {
                    const int nt = 4 * q + tt;
                    const uint32_t* bH = &bhh[tt >> 1][(tt & 1) << 1];
                    const uint32_t* bL = &bll[tt >> 1][(tt & 1) << 1];
                    mma_bf16(acc[0][nt], ah0, bH);
                    mma_bf16(acc[1][nt], ah1, bH);
                    mma_bf16(acc[0][nt], al0, bH);
                    mma_bf16(acc[1][nt], al1, bH);
                    mma_bf16(acc[0][nt], ah0, bL);
                    mma_bf16(acc[1][nt], ah1, bL);
                }
            }
            s++;
            __syncthreads();   // all warps done with this buffer
        }

        if (layer < 2) {
            // ---- epilogue: gelu -> next A planes (bf16 hi/lo, swizzled) ----
            const int r0 = (w << 5) + (l >> 2);
            #pragma unroll
            for (int m = 0; m < 2; m++) {
                const int ra = r0 + 16 * m, rb = ra + 8;
                const uint32_t sa  = (uint32_t)ra * 256 + (uint32_t)(c2 << 1);
                const uint32_t sbt = (uint32_t)rb * 256 + (uint32_t)(c2 << 1);
                #pragma unroll
                for (int nt = 0; nt < 16; nt++) {
                    float v0 = gelu_exact(acc[m][nt][0]);
                    float v1 = gelu_exact(acc[m][nt][1]);
                    float v2 = gelu_exact(acc[m][nt][2]);
                    float v3 = gelu_exact(acc[m][nt][3]);
                    uint32_t hA, lA, hB, lB;
                    split2(v0, v1, hA, lA);
                    split2(v2, v3, hB, lB);
                    uint32_t oa = sa  + (uint32_t)((nt ^ (ra & 7)) << 4);
                    uint32_t ob = sbt + (uint32_t)((nt ^ (rb & 7)) << 4);
                    *(uint32_t*)(smem + OFF_AHI + oa) = hA;
                    *(uint32_t*)(smem + OFF_ALO + oa) = lA;
                    *(uint32_t*)(smem + OFF_AHI + ob) = hB;
                    *(uint32_t*)(smem + OFF_ALO + ob) = lB;
                }
            }
            __syncthreads();
        } else {
            // ---- final: gelu*valid, reduce 32 edges -> per-node msum ----
            #pragma unroll
            for (int nt = 0; nt < 16; nt++) {
                float s0 = gelu_exact(acc[0][nt][0]) * vl4[0]
                         + gelu_exact(acc[0][nt][2]) * vl4[1]
                         + gelu_exact(acc[1][nt][0]) * vl4[2]
                         + gelu_exact(acc[1][nt][2]) * vl4[3];
                float s1 = gelu_exact(acc[0][nt][1]) * vl4[0]
                         + gelu_exact(acc[0][nt][3]) * vl4[1]
                         + gelu_exact(acc[1][nt][1]) * vl4[2]
                         + gelu_exact(acc[1][nt][3]) * vl4[3];
                #pragma unroll
                for (int sh = 4; sh < 32; sh <<= 1) {
                    s0 += __shfl_xor_sync(0xffffffffu, s0, sh);
                    s1 += __shfl_xor_sync(0xffffffffu, s1, sh);
                }
                if (l < 4) {
                    smf[(OFF_MSUM >> 2) + w * HH + 8 * nt + c2]     = s0;
                    smf[(OFF_MSUM >> 2) + w * HH + 8 * nt + c2 + 1] = s1;
                }
            }
            __syncthreads();
            #pragma unroll
            for (int g = 0; g < 4; g++) {
                float ms  = smf[(OFF_MSUM >> 2) + g * HH + tid];
                float upd = smf[(OFF_SELF >> 2) + g * HH + tid]
                          + ms * smf[(OFF_INV >> 2) + g] * smf[(OFF_NM >> 2) + g];
                g_upd[(size_t)(base_node + g) * HH + tid] = upd;
            }
        }
    }
}

// ---------------- graph norm + output assembly ----------------
__global__ __launch_bounds__(256)
void stats_kernel(const float* __restrict__ atom_mask)
{
    const int b = blockIdx.x >> 7;
    const int h = blockIdx.x & (HH - 1);
    float s = 0.0f, sq = 0.0f, c = 0.0f;
    for (int n = threadIdx.x; n < NN; n += 256) {
        float v = g_upd[((size_t)b * NN + n) * HH + h];
        s += v; sq += v * v;
        c += atom_mask[b * NN + n];
    }
    __shared__ float rs[256], rq[256], rc[256];
    rs[threadIdx.x] = s; rq[threadIdx.x] = sq; rc[threadIdx.x] = c;
    __syncthreads();
    for (int off = 128; off > 0; off >>= 1) {
        if (threadIdx.x < off) {
            rs[threadIdx.x] += rs[threadIdx.x + off];
            rq[threadIdx.x] += rq[threadIdx.x + off];
            rc[threadIdx.x] += rc[threadIdx.x + off];
        }
        __syncthreads();
    }
    if (threadIdx.x == 0) {
        float cnt = rc[0]; if (cnt == 0.0f) cnt = 1.0f;
        float mean = rs[0] / cnt;
        float var = (rq[0] - 2.0f * mean * rs[0] + (float)NN * mean * mean) / cnt;
        g_mean[b * HH + h] = mean;
        g_rstd[b * HH + h] = rsqrtf(var + 1e-5f);
    }
}

__global__ __launch_bounds__(256)
void norm_kernel(float* __restrict__ out,
                 const float* __restrict__ atom_mask,
                 const float* __restrict__ scale,
                 const float* __restrict__ shift)
{
    const int i = blockIdx.x * 256 + threadIdx.x;
    if (i >= NODES * HH) return;
    const int h  = i & (HH - 1);
    const int bn = i >> 7;
    const int b  = bn >> 12;
    const float v = g_upd[i];
    out[i] = ((v - g_mean[b * HH + h]) * g_rstd[b * HH + h] * scale[h] + shift[h])
             * atom_mask[bn];
}

__global__ __launch_bounds__(256)
void passthru_kernel(float* __restrict__ out,
                     const float* __restrict__ atom_mask,
                     const float* __restrict__ dist,
                     const int*   __restrict__ edge)
{
    const int M0 = NODES;
    const int M1 = NODES * KK;
    const int total = M0 + 2 * M1;
    const int i = blockIdx.x * 256 + threadIdx.x;
    if (i >= total) return;
    if (i < M0)            out[i] = atom_mask[i];
    else if (i < M0 + M1)  out[i] = dist[i - M0];
    else                   out[i] = (float)edge[i - M0 - M1];
}

extern "C" void kernel_launch(void* const* d_in, const int* in_sizes, int n_in,
                              void* d_out, int out_size)
{
    const float* atom_encode = (const float*)d_in[0];
    const float* atom_mask   = (const float*)d_in[1];
    const float* dist        = (const float*)d_in[2];
    const int*   edge_index  = (const int*)  d_in[3];
    const float* W0 = (const float*)d_in[4];
    const float* b0 = (const float*)d_in[5];
    const float* b1 = (const float*)d_in[7];
    const float* b2 = (const float*)d_in[9];
    const float* scale = (const float*)d_in[10];
    const float* shift = (const float*)d_in[11];
    float* out = (float*)d_out;

    cudaFuncSetAttribute(mpnn_tc, cudaFuncAttributeMaxDynamicSharedMemorySize,
                         SMEM_BYTES);
    cudaFuncSetAttribute(sbias_kernel, cudaFuncAttributeMaxDynamicSharedMemorySize,
                         SB_SMEM);

    prep_weights<<<(4 * HH * HH + 255) / 256, 256>>>(
        (const float*)d_in[4], (const float*)d_in[6], (const float*)d_in[8]);
    sbias_kernel<<<NODES / 128, 128, SB_SMEM>>>(atom_encode, atom_mask, b0);
    mpnn_tc<<<NODES / 4, 128, SMEM_BYTES>>>(atom_encode, atom_mask, dist,
                                            edge_index, W0, b1, b2);
    stats_kernel<<<BB * HH, 256>>>(atom_mask);

    const int OUT0 = NODES * HH;
    norm_kernel<<<(OUT0 + 255) / 256, 256>>>(out, atom_mask, scale, shift);

    const int PT = NODES + 2 * NODES * KK;
    if (out_size >= OUT0 + PT) {
        passthru_kernel<<<(PT + 255) / 256, 256>>>(out + OUT0, atom_mask, dist,
                                                   edge_index);
    }
}

// round 7
// speedup vs baseline: 3.2413x; 1.3071x over previous
#include <cuda_runtime.h>
#include <cuda_fp16.h>
#include <cstdint>
#include <math.h>

#define BB 4
#define NN 4096
#define KK 32
#define HH 128
#define NODES (BB*NN)

// ---------------- scratch (static, no allocation) ----------------
__device__ float g_upd[NODES * HH];          // 8 MB
__device__ float g_sbias[NODES * HH];        // 8 MB: b0 + self@W0_self per node
__device__ float g_mean[BB * HH];
__device__ float g_rstd[BB * HH];
// prepped fp16 weights: slots 0..2 = W0_src,W1,W2; slot 3 = W0_self.
// per slot: 4 quarters x (hi 8192 B | lo 8192 B), swizzled.
__device__ __align__(16) unsigned char g_Wp[4 * 65536];

// ---------------- helpers ----------------
__device__ __forceinline__ uint32_t smem_u32(const void* p) {
    uint32_t a;
    asm("{ .reg .u64 t; cvta.to.shared.u64 t, %1; cvt.u32.u64 %0, t; }"
        : "=r"(a) : "l"(p));
    return a;
}
__device__ __forceinline__ float gelu_exact(float x) {
    return 0.5f * x * (1.0f + erff(x * 0.70710678118654752440f));
}
__device__ __forceinline__ uint32_t packh2(float x, float y) {
    __half2 h = __floats2half2_rn(x, y);
    return *(uint32_t*)&h;
}
__device__ __forceinline__ void ldm4(uint32_t* r, uint32_t addr) {
    asm volatile("ldmatrix.sync.aligned.m8n8.x4.shared.b16 {%0,%1,%2,%3}, [%4];"
        : "=r"(r[0]), "=r"(r[1]), "=r"(r[2]), "=r"(r[3]) : "r"(addr));
}
__device__ __forceinline__ void mma_f16(float* c, const uint32_t* a, const uint32_t* b) {
    asm volatile(
        "mma.sync.aligned.m16n8k16.row.col.f32.f16.f16.f32 "
        "{%0,%1,%2,%3}, {%4,%5,%6,%7}, {%8,%9}, {%0,%1,%2,%3};"
        : "+f"(c[0]), "+f"(c[1]), "+f"(c[2]), "+f"(c[3])
        : "r"(a[0]), "r"(a[1]), "r"(a[2]), "r"(a[3]), "r"(b[0]), "r"(b[1]));
}
#define CP_ASYNC16(dst, src) \
    asm volatile("cp.async.cg.shared.global [%0], [%1], 16;" \
        :: "r"(dst), "l"(src) : "memory")
#define CP_COMMIT() asm volatile("cp.async.commit_group;" ::: "memory")
#define CP_WAIT1()  asm volatile("cp.async.wait_group 1;" ::: "memory")
#define CP_WAIT0()  asm volatile("cp.async.wait_group 0;" ::: "memory")

// ---------------- prep: W -> fp16 hi/lo, swizzled, quartered ----------------
__global__ void prep_weights(const float* __restrict__ W0,
                             const float* __restrict__ W1,
                             const float* __restrict__ W2)
{
    int i = blockIdx.x * blockDim.x + threadIdx.x;
    if (i >= 4 * HH * HH) return;
    int lyr = i >> 14, r = i & 16383, n = r >> 7, k = r & 127;
    float v;
    if (lyr == 0)      v = W0[k * HH + n];            // src block rows 0..127
    else if (lyr == 1) v = W1[k * HH + n];
    else if (lyr == 2) v = W2[k * HH + n];
    else               v = W0[(HH + k) * HH + n];     // self block rows 128..255
    __half h  = __float2half_rn(v);
    __half lo = __float2half_rn(v - __half2float(h));
    int q = n >> 5, nl = n & 31;
    int byte = nl * 256 + (((k >> 3) ^ (nl & 7)) << 4) + ((k & 7) << 1);
    unsigned char* base = g_Wp + (size_t)((lyr * 4 + q) * 2) * 8192;
    *(__half*)(base + byte)        = h;
    *(__half*)(base + 8192 + byte) = lo;
}

// ---------------- self-bias mini-GEMM: g_sbias = b0 + self@W0_self ----------------
// CTA = 128 nodes; single fp16 A plane (32 KB) + full W0_self hi/lo (64 KB).
#define SB_SMEM 98304
__global__ __launch_bounds__(128)
void sbias_kernel(const float* __restrict__ enc, const float* __restrict__ mask,
                  const float* __restrict__ b0)
{
    extern __shared__ char smem[];
    uint32_t sb = smem_u32(smem);
    const int tid = threadIdx.x;
    const int w = tid >> 5, l = tid & 31;
    const int base_node = blockIdx.x << 7;

    // gather masked self rows into fp16 A plane
    {
        const int node = base_node + tid;
        const float mm = mask[node];
        const float4* rp = (const float4*)(enc + (size_t)node * HH);
        const int rp7 = tid & 7;
        #pragma unroll
        for (int c = 0; c < 16; c++) {
            float4 v0 = rp[2 * c], v1 = rp[2 * c + 1];
            uint32_t u0 = packh2(v0.x * mm, v0.y * mm);
            uint32_t u1 = packh2(v0.z * mm, v0.w * mm);
            uint32_t u2 = packh2(v1.x * mm, v1.y * mm);
            uint32_t u3 = packh2(v1.z * mm, v1.w * mm);
            uint32_t off = (uint32_t)tid * 256 + (uint32_t)((c ^ rp7) << 4);
            *(uint4*)(smem + off) = make_uint4(u0, u1, u2, u3);
        }
    }
    // stage full W0_self (slot 3): 64 KB at +32768
    {
        const uint4* src = (const uint4*)(g_Wp + 3 * 65536);
        uint4* dst = (uint4*)(smem + 32768);
        #pragma unroll
        for (int i = 0; i < 32; i++) dst[tid + 128 * i] = src[tid + 128 * i];
    }
    __syncthreads();

    const int rA0 = (w << 5) + (l & 15), rA1 = rA0 + 16;
    const uint32_t cselA = (uint32_t)(l >> 4);
    const uint32_t baseA0 = sb + (uint32_t)rA0 * 256;
    const uint32_t baseA1 = sb + (uint32_t)rA1 * 256;
    const uint32_t parA0 = (uint32_t)(rA0 & 7), parA1 = (uint32_t)(rA1 & 7);
    const int rB = (l & 7) + ((l >> 4) << 3);
    const uint32_t cselB = (uint32_t)((l >> 3) & 1);
    const uint32_t parB = (uint32_t)(rB & 7);
    const int c2 = (l & 3) << 1;

    float acc[2][16][4];
    #pragma unroll
    for (int nt = 0; nt < 16; nt++) {
        float bx = b0[8 * nt + c2], by = b0[8 * nt + c2 + 1];
        #pragma unroll
        for (int m = 0; m < 2; m++) {
            acc[m][nt][0] = bx; acc[m][nt][1] = by;
            acc[m][nt][2] = bx; acc[m][nt][3] = by;
        }
    }

    #pragma unroll
    for (int q = 0; q < 4; q++) {
        const uint32_t baseBq = sb + 32768 + (uint32_t)q * 16384 + (uint32_t)rB * 256;
        #pragma unroll
        for (int ks = 0; ks < 8; ks++) {
            uint32_t ah0[4], ah1[4], bh[2][4], bl[2][4];
            const uint32_t kA = (uint32_t)(2 * ks) + cselA;
            const uint32_t kB = (uint32_t)(2 * ks) + cselB;
            ldm4(ah0, baseA0 + ((kA ^ parA0) << 4));
            ldm4(ah1, baseA1 + ((kA ^ parA1) << 4));
            #pragma unroll
            for (int jj = 0; jj < 2; jj++) {
                ldm4(bh[jj], baseBq + jj * 4096 + ((kB ^ parB) << 4));
                ldm4(bl[jj], baseBq + 8192 + jj * 4096 + ((kB ^ parB) << 4));
            }
            #pragma unroll
            for (int tt = 0; tt < 4; tt++) {
                const int nt = 4 * q + tt;
                const uint32_t* bH = &bh[tt >> 1][(tt & 1) << 1];
                const uint32_t* bL = &bl[tt >> 1][(tt & 1) << 1];
                mma_f16(acc[0][nt], ah0, bH);
                mma_f16(acc[1][nt], ah1, bH);
                mma_f16(acc[0][nt], ah0, bL);
                mma_f16(acc[1][nt], ah1, bL);
            }
        }
    }

    #pragma unroll
    for (int m = 0; m < 2; m++) {
        const int row0 = base_node + (w << 5) + (m << 4) + (l >> 2);
        #pragma unroll
        for (int nt = 0; nt < 16; nt++) {
            *(float2*)&g_sbias[(size_t)row0 * HH + 8 * nt + c2] =
                make_float2(acc[m][nt][0], acc[m][nt][1]);
            *(float2*)&g_sbias[(size_t)(row0 + 8) * HH + 8 * nt + c2] =
                make_float2(acc[m][nt][2], acc[m][nt][3]);
        }
    }
}

// ---------------- main fused kernel (R4 skeleton, fp16 2-product) ----------------
// smem layout (bytes)
#define OFF_A     0        // 32768 : A fp16 plane, 128 rows x 256B, chunk-swizzled
#define OFF_B     32768    // 32768 : double-buffered weight quarter (2 x 16 KB)
#define OFF_SELF  65536    // 2048
#define OFF_SBIAS 67584    // 2048
#define OFF_MSUM  69632    // 2048 : [4 warps][128]
#define OFF_W256  71680    // 512
#define OFF_BV    72192    // 1024
#define OFF_DE    73216    // 512
#define OFF_VLD   73728    // 512
#define OFF_INV   74240    // 16
#define OFF_NM    74256    // 16
#define SMEM_BYTES 74272

__global__ __launch_bounds__(128)
void mpnn_tc(const float* __restrict__ enc, const float* __restrict__ mask,
             const float* __restrict__ dist, const int* __restrict__ eidx,
             const float* __restrict__ W0,
             const float* __restrict__ b1, const float* __restrict__ b2)
{
    extern __shared__ char smem[];
    uint32_t sb = smem_u32(smem);
    float* smf = (float*)smem;
    const int tid = threadIdx.x;
    const int w = tid >> 5, l = tid & 31;
    const int base_node = blockIdx.x << 2;
    const int batch = base_node >> 12;

    // prologue: prefetch weight stage 0 immediately (16 KB, 128 threads)
    {
        const char* src = (const char*)g_Wp + tid * 16;
        uint32_t dst = sb + OFF_B + tid * 16;
        #pragma unroll
        for (int i = 0; i < 8; i++)
            CP_ASYNC16(dst + i * 2048, src + i * 2048);
        CP_COMMIT();
    }

    // ---- per-edge metadata (thread = edge row) ----
    const int ei = eidx[base_node * KK + tid];
    const int gsrc = batch * NN + ((ei < 0) ? 0 : ei);
    const float smask = mask[gsrc];
    smf[(OFF_DE  >> 2) + tid] = dist[base_node * KK + tid];
    smf[(OFF_VLD >> 2) + tid] = (ei >= 0) ? 1.0f : 0.0f;
    unsigned cnt = __reduce_add_sync(0xffffffffu, (ei >= 0) ? 1u : 0u);
    if (l == 0) smf[(OFF_INV >> 2) + w] = 1.0f / ((cnt == 0) ? 1.0f : (float)cnt);

    #pragma unroll
    for (int g = 0; g < 4; g++) {
        float mm = mask[base_node + g];
        smf[(OFF_SELF  >> 2) + g * HH + tid] =
            enc[(size_t)(base_node + g) * HH + tid] * mm;
        smf[(OFF_SBIAS >> 2) + g * HH + tid] =
            g_sbias[(size_t)(base_node + g) * HH + tid];
    }
    if (tid < 4) smf[(OFF_NM >> 2) + tid] = mask[base_node + tid];
    smf[(OFF_W256 >> 2) + tid]      = W0[256 * HH + tid];
    smf[(OFF_BV   >> 2) + tid]      = b1[tid];
    smf[(OFF_BV   >> 2) + HH + tid] = b2[tid];

    // ---- gather neighbor features -> A plane (fp16, swizzled) ----
    {
        const float4* rp = (const float4*)(enc + (size_t)gsrc * HH);
        const int rp7 = tid & 7;
        #pragma unroll
        for (int c = 0; c < 16; c++) {
            float4 v0 = rp[2 * c], v1 = rp[2 * c + 1];
            uint32_t u0 = packh2(v0.x * smask, v0.y * smask);
            uint32_t u1 = packh2(v0.z * smask, v0.w * smask);
            uint32_t u2 = packh2(v1.x * smask, v1.y * smask);
            uint32_t u3 = packh2(v1.z * smask, v1.w * smask);
            uint32_t off = (uint32_t)tid * 256 + (uint32_t)((c ^ rp7) << 4);
            *(uint4*)(smem + OFF_A + off) = make_uint4(u0, u1, u2, u3);
        }
    }

    // ---- lane constants for ldmatrix addressing ----
    const int rA0 = (w << 5) + (l & 15), rA1 = rA0 + 16;
    const uint32_t cselA = (uint32_t)(l >> 4);
    const uint32_t baseA0 = sb + OFF_A + (uint32_t)rA0 * 256;
    const uint32_t baseA1 = sb + OFF_A + (uint32_t)rA1 * 256;
    const uint32_t parA0 = (uint32_t)(rA0 & 7), parA1 = (uint32_t)(rA1 & 7);
    const int rB = (l & 7) + ((l >> 4) << 3);
    const uint32_t cselB = (uint32_t)((l >> 3) & 1);
    const uint32_t parB = (uint32_t)(rB & 7);
    const int c2 = (l & 3) << 1;

    float de4[4], vl4[4];
    #pragma unroll
    for (int ri = 0; ri < 4; ri++) {
        int rr = (w << 5) + (l >> 2) + 8 * ri;
        de4[ri] = smf[(OFF_DE  >> 2) + rr];
        vl4[ri] = smf[(OFF_VLD >> 2) + rr];
    }
    __syncthreads();   // A plane + small tables visible

    float acc[2][16][4];
    int s = 0;   // global weight stage 0..11

    #pragma unroll 1
    for (int layer = 0; layer < 3; layer++) {
        // ---- init acc with bias ----
        if (layer == 0) {
            #pragma unroll
            for (int nt = 0; nt < 16; nt++) {
                float2 sb2 = *(float2*)&smf[(OFF_SBIAS >> 2) + w * HH + 8 * nt + c2];
                float2 w2  = *(float2*)&smf[(OFF_W256  >> 2) + 8 * nt + c2];
                #pragma unroll
                for (int m = 0; m < 2; m++) {
                    acc[m][nt][0] = fmaf(de4[2 * m],     w2.x, sb2.x);
                    acc[m][nt][1] = fmaf(de4[2 * m],     w2.y, sb2.y);
                    acc[m][nt][2] = fmaf(de4[2 * m + 1], w2.x, sb2.x);
                    acc[m][nt][3] = fmaf(de4[2 * m + 1], w2.y, sb2.y);
                }
            }
        } else {
            const float* bv = &smf[(OFF_BV >> 2) + (layer - 1) * HH];
            #pragma unroll
            for (int nt = 0; nt < 16; nt++) {
                float2 b2v = *(float2*)&bv[8 * nt + c2];
                #pragma unroll
                for (int m = 0; m < 2; m++) {
                    acc[m][nt][0] = b2v.x; acc[m][nt][1] = b2v.y;
                    acc[m][nt][2] = b2v.x; acc[m][nt][3] = b2v.y;
                }
            }
        }

        // ---- 4 weight quarters; double-buffered cp.async pipeline ----
        #pragma unroll
        for (int q = 0; q < 4; q++) {
            if (s + 1 < 12) {
                const char* src = (const char*)g_Wp + (s + 1) * 16384 + tid * 16;
                uint32_t dst = sb + OFF_B + ((s + 1) & 1) * 16384 + tid * 16;
                #pragma unroll
                for (int i = 0; i < 8; i++)
                    CP_ASYNC16(dst + i * 2048, src + i * 2048);
                CP_COMMIT();
                CP_WAIT1();
            } else {
                CP_WAIT0();
            }
            __syncthreads();   // stage s data visible

            const uint32_t baseB = sb + OFF_B + (uint32_t)((s & 1) * 16384)
                                 + (uint32_t)rB * 256;
            #pragma unroll
            for (int ks = 0; ks < 8; ks++) {
                uint32_t ah0[4], ah1[4], bh[2][4], bl[2][4];
                const uint32_t kA = (uint32_t)(2 * ks) + cselA;
                const uint32_t kB = (uint32_t)(2 * ks) + cselB;
                ldm4(ah0, baseA0 + ((kA ^ parA0) << 4));
                ldm4(ah1, baseA1 + ((kA ^ parA1) << 4));
                #pragma unroll
                for (int jj = 0; jj < 2; jj++) {
                    ldm4(bh[jj], baseB + jj * 4096 + ((kB ^ parB) << 4));
                    ldm4(bl[jj], baseB + 8192 + jj * 4096 + ((kB ^ parB) << 4));
                }
                #pragma unroll
                for (int tt = 0; tt < 4; tt++) {
                    const int nt = 4 * q + tt;
                    const uint32_t* bH = &bh[tt >> 1][(tt & 1) << 1];
                    const uint32_t* bL = &bl[tt >> 1][(tt & 1) << 1];
                    mma_f16(acc[0][nt], ah0, bH);
                    mma_f16(acc[1][nt], ah1, bH);
                    mma_f16(acc[0][nt], ah0, bL);
                    mma_f16(acc[1][nt], ah1, bL);
                }
            }
            s++;
            __syncthreads();   // all warps done with this buffer
        }

        if (layer < 2) {
            // ---- epilogue: gelu -> A plane (fp16, swizzled) ----
            const int r0 = (w << 5) + (l >> 2);
            #pragma unroll
            for (int m = 0; m < 2; m++) {
                const int ra = r0 + 16 * m, rb = ra + 8;
                const uint32_t sa  = (uint32_t)ra * 256 + (uint32_t)((l & 3) << 2);
                const uint32_t sbt = (uint32_t)rb * 256 + (uint32_t)((l & 3) << 2);
                #pragma unroll
                for (int nt = 0; nt < 16; nt++) {
                    uint32_t hA = packh2(gelu_exact(acc[m][nt][0]),
                                         gelu_exact(acc[m][nt][1]));
                    uint32_t hB = packh2(gelu_exact(acc[m][nt][2]),
                                         gelu_exact(acc[m][nt][3]));
                    uint32_t oa = sa  + (uint32_t)((nt ^ (ra & 7)) << 4);
                    uint32_t ob = sbt + (uint32_t)((nt ^ (rb & 7)) << 4);
                    *(uint32_t*)(smem + OFF_A + oa) = hA;
                    *(uint32_t*)(smem + OFF_A + ob) = hB;
                }
            }
            __syncthreads();
        } else {
            // ---- final: gelu*valid, reduce 32 edges -> per-node msum ----
            #pragma unroll
            for (int nt = 0; nt < 16; nt++) {
                float s0 = gelu_exact(acc[0][nt][0]) * vl4[0]
                         + gelu_exact(acc[0][nt][2]) * vl4[1]
                         + gelu_exact(acc[1][nt][0]) * vl4[2]
                         + gelu_exact(acc[1][nt][2]) * vl4[3];
                float s1 = gelu_exact(acc[0][nt][1]) * vl4[0]
                         + gelu_exact(acc[0][nt][3]) * vl4[1]
                         + gelu_exact(acc[1][nt][1]) * vl4[2]
                         + gelu_exact(acc[1][nt][3]) * vl4[3];
                #pragma unroll
                for (int sh = 4; sh < 32; sh <<= 1) {
                    s0 += __shfl_xor_sync(0xffffffffu, s0, sh);
                    s1 += __shfl_xor_sync(0xffffffffu, s1, sh);
                }
                if (l < 4) {
                    smf[(OFF_MSUM >> 2) + w * HH + 8 * nt + c2]     = s0;
                    smf[(OFF_MSUM >> 2) + w * HH + 8 * nt + c2 + 1] = s1;
                }
            }
            __syncthreads();
            #pragma unroll
            for (int g = 0; g < 4; g++) {
                float ms  = smf[(OFF_MSUM >> 2) + g * HH + tid];
                float upd = smf[(OFF_SELF >> 2) + g * HH + tid]
                          + ms * smf[(OFF_INV >> 2) + g] * smf[(OFF_NM >> 2) + g];
                g_upd[(size_t)(base_node + g) * HH + tid] = upd;
            }
        }
    }
}

// ---------------- graph norm + output assembly ----------------
__global__ __launch_bounds__(256)
void stats_kernel(const float* __restrict__ atom_mask)
{
    const int b = blockIdx.x >> 7;
    const int h = blockIdx.x & (HH - 1);
    float s = 0.0f, sq = 0.0f, c = 0.0f;
    for (int n = threadIdx.x; n < NN; n += 256) {
        float v = g_upd[((size_t)b * NN + n) * HH + h];
        s += v; sq += v * v;
        c += atom_mask[b * NN + n];
    }
    __shared__ float rs[256], rq[256], rc[256];
    rs[threadIdx.x] = s; rq[threadIdx.x] = sq; rc[threadIdx.x] = c;
    __syncthreads();
    for (int off = 128; off > 0; off >>= 1) {
        if (threadIdx.x < off) {
            rs[threadIdx.x] += rs[threadIdx.x + off];
            rq[threadIdx.x] += rq[threadIdx.x + off];
            rc[threadIdx.x] += rc[threadIdx.x + off];
        }
        __syncthreads();
    }
    if (threadIdx.x == 0) {
        float cnt = rc[0]; if (cnt == 0.0f) cnt = 1.0f;
        float mean = rs[0] / cnt;
        float var = (rq[0] - 2.0f * mean * rs[0] + (float)NN * mean * mean) / cnt;
        g_mean[b * HH + h] = mean;
        g_rstd[b * HH + h] = rsqrtf(var + 1e-5f);
    }
}

__global__ __launch_bounds__(256)
void norm_kernel(float* __restrict__ out,
                 const float* __restrict__ atom_mask,
                 const float* __restrict__ scale,
                 const float* __restrict__ shift)
{
    const int i = blockIdx.x * 256 + threadIdx.x;
    if (i >= NODES * HH) return;
    const int h  = i & (HH - 1);
    const int bn = i >> 7;
    const int b  = bn >> 12;
    const float v = g_upd[i];
    out[i] = ((v - g_mean[b * HH + h]) * g_rstd[b * HH + h] * scale[h] + shift[h])
             * atom_mask[bn];
}

__global__ __launch_bounds__(256)
void passthru_kernel(float* __restrict__ out,
                     const float* __restrict__ atom_mask,
                     const float* __restrict__ dist,
                     const int*   __restrict__ edge)
{
    const int M0 = NODES;
    const int M1 = NODES * KK;
    const int total = M0 + 2 * M1;
    const int i = blockIdx.x * 256 + threadIdx.x;
    if (i >= total) return;
    if (i < M0)            out[i] = atom_mask[i];
    else if (i < M0 + M1)  out[i] = dist[i - M0];
    else                   out[i] = (float)edge[i - M0 - M1];
}

extern "C" void kernel_launch(void* const* d_in, const int* in_sizes, int n_in,
                              void* d_out, int out_size)
{
    const float* atom_encode = (const float*)d_in[0];
    const float* atom_mask   = (const float*)d_in[1];
    const float* dist        = (const float*)d_in[2];
    const int*   edge_index  = (const int*)  d_in[3];
    const float* W0 = (const float*)d_in[4];
    const float* b0 = (const float*)d_in[5];
    const float* b1 = (const float*)d_in[7];
    const float* b2 = (const float*)d_in[9];
    const float* scale = (const float*)d_in[10];
    const float* shift = (const float*)d_in[11];
    float* out = (float*)d_out;

    cudaFuncSetAttribute(mpnn_tc, cudaFuncAttributeMaxDynamicSharedMemorySize,
                         SMEM_BYTES);
    cudaFuncSetAttribute(sbias_kernel, cudaFuncAttributeMaxDynamicSharedMemorySize,
                         SB_SMEM);

    prep_weights<<<(4 * HH * HH + 255) / 256, 256>>>(
        (const float*)d_in[4], (const float*)d_in[6], (const float*)d_in[8]);
    sbias_kernel<<<NODES / 128, 128, SB_SMEM>>>(atom_encode, atom_mask, b0);
    mpnn_tc<<<NODES / 4, 128, SMEM_BYTES>>>(atom_encode, atom_mask, dist,
                                            edge_index, W0, b1, b2);
    stats_kernel<<<BB * HH, 256>>>(atom_mask);

    const int OUT0 = NODES * HH;
    norm_kernel<<<(OUT0 + 255) / 256, 256>>>(out, atom_mask, scale, shift);

    const int PT = NODES + 2 * NODES * KK;
    if (out_size >= OUT0 + PT) {
        passthru_kernel<<<(PT + 255) / 256, 256>>>(out + OUT0, atom_mask, dist,
                                                   edge_index);
    }
}

// round 8
// speedup vs baseline: 3.9388x; 1.2152x over previous
#include <cuda_runtime.h>
#include <cuda_fp16.h>
#include <cstdint>
#include <math.h>

#define BB 4
#define NN 4096
#define KK 32
#define HH 128
#define NODES (BB*NN)

// ---------------- scratch (static, no allocation) ----------------
__device__ float g_upd[NODES * HH];          // 8 MB
__device__ float g_sbias[NODES * HH];        // 8 MB: b0 + self@W0_self per node
__device__ float g_mean[BB * HH];
__device__ float g_rstd[BB * HH];
// prepped fp16 weights:
//   [0, 98304)       : layers 0..2, hi-only, 32 KB each (4 quarters x 8 KB, swizzled)
//   [98304, 163840)  : W0_self hi/lo, 4 quarters x (hi 8 KB | lo 8 KB)
__device__ __align__(16) unsigned char g_Wp[163840];

// ---------------- helpers ----------------
__device__ __forceinline__ uint32_t smem_u32(const void* p) {
    uint32_t a;
    asm("{ .reg .u64 t; cvta.to.shared.u64 t, %1; cvt.u32.u64 %0, t; }"
        : "=r"(a) : "l"(p));
    return a;
}
__device__ __forceinline__ float gelu_exact(float x) {
    return 0.5f * x * (1.0f + erff(x * 0.70710678118654752440f));
}
__device__ __forceinline__ uint32_t packh2(float x, float y) {
    __half2 h = __floats2half2_rn(x, y);
    return *(uint32_t*)&h;
}
__device__ __forceinline__ void ldm4(uint32_t* r, uint32_t addr) {
    asm volatile("ldmatrix.sync.aligned.m8n8.x4.shared.b16 {%0,%1,%2,%3}, [%4];"
        : "=r"(r[0]), "=r"(r[1]), "=r"(r[2]), "=r"(r[3]) : "r"(addr));
}
__device__ __forceinline__ void mma_f16(float* c, const uint32_t* a, const uint32_t* b) {
    asm volatile(
        "mma.sync.aligned.m16n8k16.row.col.f32.f16.f16.f32 "
        "{%0,%1,%2,%3}, {%4,%5,%6,%7}, {%8,%9}, {%0,%1,%2,%3};"
        : "+f"(c[0]), "+f"(c[1]), "+f"(c[2]), "+f"(c[3])
        : "r"(a[0]), "r"(a[1]), "r"(a[2]), "r"(a[3]), "r"(b[0]), "r"(b[1]));
}
#define CP_ASYNC16(dst, src) \
    asm volatile("cp.async.cg.shared.global [%0], [%1], 16;" \
        :: "r"(dst), "l"(src) : "memory")
#define CP_COMMIT() asm volatile("cp.async.commit_group;" ::: "memory")
#define CP_WAIT1()  asm volatile("cp.async.wait_group 1;" ::: "memory")
#define CP_WAIT0()  asm volatile("cp.async.wait_group 0;" ::: "memory")

// ---------------- prep: W -> fp16, swizzled, quartered ----------------
__global__ void prep_weights(const float* __restrict__ W0,
                             const float* __restrict__ W1,
                             const float* __restrict__ W2)
{
    int i = blockIdx.x * blockDim.x + threadIdx.x;
    if (i >= 4 * HH * HH) return;
    int lyr = i >> 14, r = i & 16383, n = r >> 7, k = r & 127;
    float v;
    if (lyr == 0)      v = W0[k * HH + n];            // src block rows 0..127
    else if (lyr == 1) v = W1[k * HH + n];
    else if (lyr == 2) v = W2[k * HH + n];
    else               v = W0[(HH + k) * HH + n];     // self block rows 128..255
    __half h = __float2half_rn(v);
    int q = n >> 5, nl = n & 31;
    int byte = nl * 256 + (((k >> 3) ^ (nl & 7)) << 4) + ((k & 7) << 1);
    if (lyr < 3) {
        *(__half*)(g_Wp + lyr * 32768 + q * 8192 + byte) = h;
    } else {
        __half lo = __float2half_rn(v - __half2float(h));
        unsigned char* base = g_Wp + 98304 + q * 16384;
        *(__half*)(base + byte)        = h;
        *(__half*)(base + 8192 + byte) = lo;
    }
}

// ---------------- self-bias mini-GEMM: g_sbias = b0 + self@W0_self ----------------
// CTA = 128 nodes; fp16 A plane (32 KB) + full W0_self hi/lo (64 KB). 2-product.
#define SB_SMEM 98304
__global__ __launch_bounds__(128)
void sbias_kernel(const float* __restrict__ enc, const float* __restrict__ mask,
                  const float* __restrict__ b0)
{
    extern __shared__ char smem[];
    uint32_t sb = smem_u32(smem);
    const int tid = threadIdx.x;
    const int w = tid >> 5, l = tid & 31;
    const int base_node = blockIdx.x << 7;

    // gather masked self rows into fp16 A plane
    {
        const int node = base_node + tid;
        const float mm = mask[node];
        const float4* rp = (const float4*)(enc + (size_t)node * HH);
        const int rp7 = tid & 7;
        #pragma unroll
        for (int c = 0; c < 16; c++) {
            float4 v0 = rp[2 * c], v1 = rp[2 * c + 1];
            uint32_t u0 = packh2(v0.x * mm, v0.y * mm);
            uint32_t u1 = packh2(v0.z * mm, v0.w * mm);
            uint32_t u2 = packh2(v1.x * mm, v1.y * mm);
            uint32_t u3 = packh2(v1.z * mm, v1.w * mm);
            uint32_t off = (uint32_t)tid * 256 + (uint32_t)((c ^ rp7) << 4);
            *(uint4*)(smem + off) = make_uint4(u0, u1, u2, u3);
        }
    }
    // stage full W0_self hi/lo: 64 KB at +32768
    {
        const uint4* src = (const uint4*)(g_Wp + 98304);
        uint4* dst = (uint4*)(smem + 32768);
        #pragma unroll
        for (int i = 0; i < 32; i++) dst[tid + 128 * i] = src[tid + 128 * i];
    }
    __syncthreads();

    const int rA0 = (w << 5) + (l & 15), rA1 = rA0 + 16;
    const uint32_t cselA = (uint32_t)(l >> 4);
    const uint32_t baseA0 = sb + (uint32_t)rA0 * 256;
    const uint32_t baseA1 = sb + (uint32_t)rA1 * 256;
    const uint32_t parA0 = (uint32_t)(rA0 & 7), parA1 = (uint32_t)(rA1 & 7);
    const int rB = (l & 7) + ((l >> 4) << 3);
    const uint32_t cselB = (uint32_t)((l >> 3) & 1);
    const uint32_t parB = (uint32_t)(rB & 7);
    const int c2 = (l & 3) << 1;

    float acc[2][16][4];
    #pragma unroll
    for (int nt = 0; nt < 16; nt++) {
        float bx = b0[8 * nt + c2], by = b0[8 * nt + c2 + 1];
        #pragma unroll
        for (int m = 0; m < 2; m++) {
            acc[m][nt][0] = bx; acc[m][nt][1] = by;
            acc[m][nt][2] = bx; acc[m][nt][3] = by;
        }
    }

    #pragma unroll
    for (int q = 0; q < 4; q++) {
        const uint32_t baseBq = sb + 32768 + (uint32_t)q * 16384 + (uint32_t)rB * 256;
        #pragma unroll
        for (int ks = 0; ks < 8; ks++) {
            uint32_t ah0[4], ah1[4], bh[2][4], bl[2][4];
            const uint32_t kA = (uint32_t)(2 * ks) + cselA;
            const uint32_t kB = (uint32_t)(2 * ks) + cselB;
            ldm4(ah0, baseA0 + ((kA ^ parA0) << 4));
            ldm4(ah1, baseA1 + ((kA ^ parA1) << 4));
            #pragma unroll
            for (int jj = 0; jj < 2; jj++) {
                ldm4(bh[jj], baseBq + jj * 4096 + ((kB ^ parB) << 4));
                ldm4(bl[jj], baseBq + 8192 + jj * 4096 + ((kB ^ parB) << 4));
            }
            #pragma unroll
            for (int tt = 0; tt < 4; tt++) {
                const int nt = 4 * q + tt;
                const uint32_t* bH = &bh[tt >> 1][(tt & 1) << 1];
                const uint32_t* bL = &bl[tt >> 1][(tt & 1) << 1];
                mma_f16(acc[0][nt], ah0, bH);
                mma_f16(acc[1][nt], ah1, bH);
                mma_f16(acc[0][nt], ah0, bL);
                mma_f16(acc[1][nt], ah1, bL);
            }
        }
    }

    #pragma unroll
    for (int m = 0; m < 2; m++) {
        const int row0 = base_node + (w << 5) + (m << 4) + (l >> 2);
        #pragma unroll
        for (int nt = 0; nt < 16; nt++) {
            *(float2*)&g_sbias[(size_t)row0 * HH + 8 * nt + c2] =
                make_float2(acc[m][nt][0], acc[m][nt][1]);
            *(float2*)&g_sbias[(size_t)(row0 + 8) * HH + 8 * nt + c2] =
                make_float2(acc[m][nt][2], acc[m][nt][3]);
        }
    }
}

// ---------------- main fused kernel (128 threads; hi-only, full-layer staging) ----
// smem layout (bytes)
#define OFF_A     0        // 32768 : A fp16 plane, 128 rows x 256B, chunk-swizzled
#define OFF_B     32768    // 65536 : double-buffered full-layer weights (2 x 32 KB)
#define OFF_SELF  98304    // 2048
#define OFF_SBIAS 100352   // 2048
#define OFF_MSUM  102400   // 2048 : [4 warps][128]
#define OFF_W256  104448   // 512
#define OFF_BV    104960   // 1024
#define OFF_DE    105984   // 512
#define OFF_VLD   106496   // 512
#define OFF_INV   107008   // 16
#define OFF_NM    107024   // 16
#define SMEM_BYTES 107040

__global__ __launch_bounds__(128)
void mpnn_tc(const float* __restrict__ enc, const float* __restrict__ mask,
             const float* __restrict__ dist, const int* __restrict__ eidx,
             const float* __restrict__ W0,
             const float* __restrict__ b1, const float* __restrict__ b2)
{
    extern __shared__ char smem[];
    uint32_t sb = smem_u32(smem);
    float* smf = (float*)smem;
    const int tid = threadIdx.x;
    const int w = tid >> 5, l = tid & 31;
    const int base_node = blockIdx.x << 2;
    const int batch = base_node >> 12;

    // prologue: prefetch layer-0 weights (32 KB) immediately
    {
        const char* src = (const char*)g_Wp + tid * 16;
        uint32_t dst = sb + OFF_B + tid * 16;
        #pragma unroll
        for (int i = 0; i < 16; i++)
            CP_ASYNC16(dst + i * 2048, src + i * 2048);
        CP_COMMIT();
    }

    // ---- per-edge metadata (thread = edge row) ----
    const int ei = eidx[base_node * KK + tid];
    const int gsrc = batch * NN + ((ei < 0) ? 0 : ei);
    const float smask = mask[gsrc];
    smf[(OFF_DE  >> 2) + tid] = dist[base_node * KK + tid];
    smf[(OFF_VLD >> 2) + tid] = (ei >= 0) ? 1.0f : 0.0f;
    unsigned cnt = __reduce_add_sync(0xffffffffu, (ei >= 0) ? 1u : 0u);
    if (l == 0) smf[(OFF_INV >> 2) + w] = 1.0f / ((cnt == 0) ? 1.0f : (float)cnt);

    #pragma unroll
    for (int g = 0; g < 4; g++) {
        float mm = mask[base_node + g];
        smf[(OFF_SELF  >> 2) + g * HH + tid] =
            enc[(size_t)(base_node + g) * HH + tid] * mm;
        smf[(OFF_SBIAS >> 2) + g * HH + tid] =
            g_sbias[(size_t)(base_node + g) * HH + tid];
    }
    if (tid < 4) smf[(OFF_NM >> 2) + tid] = mask[base_node + tid];
    smf[(OFF_W256 >> 2) + tid]      = W0[256 * HH + tid];
    smf[(OFF_BV   >> 2) + tid]      = b1[tid];
    smf[(OFF_BV   >> 2) + HH + tid] = b2[tid];

    // ---- gather neighbor features -> A plane (fp16, swizzled) ----
    {
        const float4* rp = (const float4*)(enc + (size_t)gsrc * HH);
        const int rp7 = tid & 7;
        #pragma unroll
        for (int c = 0; c < 16; c++) {
            float4 v0 = rp[2 * c], v1 = rp[2 * c + 1];
            uint32_t u0 = packh2(v0.x * smask, v0.y * smask);
            uint32_t u1 = packh2(v0.z * smask, v0.w * smask);
            uint32_t u2 = packh2(v1.x * smask, v1.y * smask);
            uint32_t u3 = packh2(v1.z * smask, v1.w * smask);
            uint32_t off = (uint32_t)tid * 256 + (uint32_t)((c ^ rp7) << 4);
            *(uint4*)(smem + OFF_A + off) = make_uint4(u0, u1, u2, u3);
        }
    }

    // ---- lane constants for ldmatrix addressing ----
    const int rA0 = (w << 5) + (l & 15), rA1 = rA0 + 16;
    const uint32_t cselA = (uint32_t)(l >> 4);
    const uint32_t baseA0 = sb + OFF_A + (uint32_t)rA0 * 256;
    const uint32_t baseA1 = sb + OFF_A + (uint32_t)rA1 * 256;
    const uint32_t parA0 = (uint32_t)(rA0 & 7), parA1 = (uint32_t)(rA1 & 7);
    const int rB = (l & 7) + ((l >> 4) << 3);
    const uint32_t cselB = (uint32_t)((l >> 3) & 1);
    const uint32_t parB = (uint32_t)(rB & 7);
    const int c2 = (l & 3) << 1;

    float de4[4], vl4[4];
    #pragma unroll
    for (int ri = 0; ri < 4; ri++) {
        int rr = (w << 5) + (l >> 2) + 8 * ri;
        de4[ri] = smf[(OFF_DE  >> 2) + rr];
        vl4[ri] = smf[(OFF_VLD >> 2) + rr];
    }
    __syncthreads();   // A plane + small tables visible

    float acc[2][16][4];

    #pragma unroll 1
    for (int layer = 0; layer < 3; layer++) {
        // ---- init acc with bias ----
        if (layer == 0) {
            #pragma unroll
            for (int nt = 0; nt < 16; nt++) {
                float2 sb2 = *(float2*)&smf[(OFF_SBIAS >> 2) + w * HH + 8 * nt + c2];
                float2 w2  = *(float2*)&smf[(OFF_W256  >> 2) + 8 * nt + c2];
                #pragma unroll
                for (int m = 0; m < 2; m++) {
                    acc[m][nt][0] = fmaf(de4[2 * m],     w2.x, sb2.x);
                    acc[m][nt][1] = fmaf(de4[2 * m],     w2.y, sb2.y);
                    acc[m][nt][2] = fmaf(de4[2 * m + 1], w2.x, sb2.x);
                    acc[m][nt][3] = fmaf(de4[2 * m + 1], w2.y, sb2.y);
                }
            }
        } else {
            const float* bv = &smf[(OFF_BV >> 2) + (layer - 1) * HH];
            #pragma unroll
            for (int nt = 0; nt < 16; nt++) {
                float2 b2v = *(float2*)&bv[8 * nt + c2];
                #pragma unroll
                for (int m = 0; m < 2; m++) {
                    acc[m][nt][0] = b2v.x; acc[m][nt][1] = b2v.y;
                    acc[m][nt][2] = b2v.x; acc[m][nt][3] = b2v.y;
                }
            }
        }

        // ---- prefetch next layer's weights; wait for current ----
        if (layer + 1 < 3) {
            const char* src = (const char*)g_Wp + (layer + 1) * 32768 + tid * 16;
            uint32_t dst = sb + OFF_B + ((layer + 1) & 1) * 32768 + tid * 16;
            #pragma unroll
            for (int i = 0; i < 16; i++)
                CP_ASYNC16(dst + i * 2048, src + i * 2048);
            CP_COMMIT();
            CP_WAIT1();
        } else {
            CP_WAIT0();
        }
        __syncthreads();   // current layer weights visible to all warps

        // ---- full layer: 4 quarters x 8 k-steps, hi product only ----
        const uint32_t baseBL = sb + OFF_B + (uint32_t)((layer & 1) * 32768)
                              + (uint32_t)rB * 256;
        #pragma unroll
        for (int q = 0; q < 4; q++) {
            const uint32_t baseBq = baseBL + (uint32_t)q * 8192;
            #pragma unroll
            for (int ks = 0; ks < 8; ks++) {
                uint32_t ah0[4], ah1[4], bh[2][4];
                const uint32_t kA = (uint32_t)(2 * ks) + cselA;
                const uint32_t kB = (uint32_t)(2 * ks) + cselB;
                ldm4(ah0, baseA0 + ((kA ^ parA0) << 4));
                ldm4(ah1, baseA1 + ((kA ^ parA1) << 4));
                #pragma unroll
                for (int jj = 0; jj < 2; jj++)
                    ldm4(bh[jj], baseBq + jj * 4096 + ((kB ^ parB) << 4));
                #pragma unroll
                for (int tt = 0; tt < 4; tt++) {
                    const int nt = 4 * q + tt;
                    const uint32_t* bH = &bh[tt >> 1][(tt & 1) << 1];
                    mma_f16(acc[0][nt], ah0, bH);
                    mma_f16(acc[1][nt], ah1, bH);
                }
            }
        }
        __syncthreads();   // all warps done with A + this weight buffer

        if (layer < 2) {
            // ---- epilogue: gelu -> A plane (fp16, swizzled) ----
            const int r0 = (w << 5) + (l >> 2);
            #pragma unroll
            for (int m = 0; m < 2; m++) {
                const int ra = r0 + 16 * m, rb = ra + 8;
                const uint32_t sa  = (uint32_t)ra * 256 + (uint32_t)((l & 3) << 2);
                const uint32_t sbt = (uint32_t)rb * 256 + (uint32_t)((l & 3) << 2);
                #pragma unroll
                for (int nt = 0; nt < 16; nt++) {
                    uint32_t hA = packh2(gelu_exact(acc[m][nt][0]),
                                         gelu_exact(acc[m][nt][1]));
                    uint32_t hB = packh2(gelu_exact(acc[m][nt][2]),
                                         gelu_exact(acc[m][nt][3]));
                    uint32_t oa = sa  + (uint32_t)((nt ^ (ra & 7)) << 4);
                    uint32_t ob = sbt + (uint32_t)((nt ^ (rb & 7)) << 4);
                    *(uint32_t*)(smem + OFF_A + oa) = hA;
                    *(uint32_t*)(smem + OFF_A + ob) = hB;
                }
            }
            __syncthreads();
        } else {
            // ---- final: gelu*valid, reduce 32 edges -> per-node msum ----
            #pragma unroll
            for (int nt = 0; nt < 16; nt++) {
                float s0 = gelu_exact(acc[0][nt][0]) * vl4[0]
                         + gelu_exact(acc[0][nt][2]) * vl4[1]
                         + gelu_exact(acc[1][nt][0]) * vl4[2]
                         + gelu_exact(acc[1][nt][2]) * vl4[3];
                float s1 = gelu_exact(acc[0][nt][1]) * vl4[0]
                         + gelu_exact(acc[0][nt][3]) * vl4[1]
                         + gelu_exact(acc[1][nt][1]) * vl4[2]
                         + gelu_exact(acc[1][nt][3]) * vl4[3];
                #pragma unroll
                for (int sh = 4; sh < 32; sh <<= 1) {
                    s0 += __shfl_xor_sync(0xffffffffu, s0, sh);
                    s1 += __shfl_xor_sync(0xffffffffu, s1, sh);
                }
                if (l < 4) {
                    smf[(OFF_MSUM >> 2) + w * HH + 8 * nt + c2]     = s0;
                    smf[(OFF_MSUM >> 2) + w * HH + 8 * nt + c2 + 1] = s1;
                }
            }
            __syncthreads();
            #pragma unroll
            for (int g = 0; g < 4; g++) {
                float ms  = smf[(OFF_MSUM >> 2) + g * HH + tid];
                float upd = smf[(OFF_SELF >> 2) + g * HH + tid]
                          + ms * smf[(OFF_INV >> 2) + g] * smf[(OFF_NM >> 2) + g];
                g_upd[(size_t)(base_node + g) * HH + tid] = upd;
            }
        }
    }
}

// ---------------- graph norm + output assembly ----------------
__global__ __launch_bounds__(256)
void stats_kernel(const float* __restrict__ atom_mask)
{
    const int b = blockIdx.x >> 7;
    const int h = blockIdx.x & (HH - 1);
    float s = 0.0f, sq = 0.0f, c = 0.0f;
    for (int n = threadIdx.x; n < NN; n += 256) {
        float v = g_upd[((size_t)b * NN + n) * HH + h];
        s += v; sq += v * v;
        c += atom_mask[b * NN + n];
    }
    __shared__ float rs[256], rq[256], rc[256];
    rs[threadIdx.x] = s; rq[threadIdx.x] = sq; rc[threadIdx.x] = c;
    __syncthreads();
    for (int off = 128; off > 0; off >>= 1) {
        if (threadIdx.x < off) {
            rs[threadIdx.x] += rs[threadIdx.x + off];
            rq[threadIdx.x] += rq[threadIdx.x + off];
            rc[threadIdx.x] += rc[threadIdx.x + off];
        }
        __syncthreads();
    }
    if (threadIdx.x == 0) {
        float cnt = rc[0]; if (cnt == 0.0f) cnt = 1.0f;
        float mean = rs[0] / cnt;
        float var = (rq[0] - 2.0f * mean * rs[0] + (float)NN * mean * mean) / cnt;
        g_mean[b * HH + h] = mean;
        g_rstd[b * HH + h] = rsqrtf(var + 1e-5f);
    }
}

__global__ __launch_bounds__(256)
void norm_kernel(float* __restrict__ out,
                 const float* __restrict__ atom_mask,
                 const float* __restrict__ scale,
                 const float* __restrict__ shift)
{
    const int i = blockIdx.x * 256 + threadIdx.x;
    if (i >= NODES * HH) return;
    const int h  = i & (HH - 1);
    const int bn = i >> 7;
    const int b  = bn >> 12;
    const float v = g_upd[i];
    out[i] = ((v - g_mean[b * HH + h]) * g_rstd[b * HH + h] * scale[h] + shift[h])
             * atom_mask[bn];
}

__global__ __launch_bounds__(256)
void passthru_kernel(float* __restrict__ out,
                     const float* __restrict__ atom_mask,
                     const float* __restrict__ dist,
                     const int*   __restrict__ edge)
{
    const int M0 = NODES;
    const int M1 = NODES * KK;
    const int total = M0 + 2 * M1;
    const int i = blockIdx.x * 256 + threadIdx.x;
    if (i >= total) return;
    if (i < M0)            out[i] = atom_mask[i];
    else if (i < M0 + M1)  out[i] = dist[i - M0];
    else                   out[i] = (float)edge[i - M0 - M1];
}

extern "C" void kernel_launch(void* const* d_in, const int* in_sizes, int n_in,
                              void* d_out, int out_size)
{
    const float* atom_encode = (const float*)d_in[0];
    const float* atom_mask   = (const float*)d_in[1];
    const float* dist        = (const float*)d_in[2];
    const int*   edge_index  = (const int*)  d_in[3];
    const float* W0 = (const float*)d_in[4];
    const float* b0 = (const float*)d_in[5];
    const float* b1 = (const float*)d_in[7];
    const float* b2 = (const float*)d_in[9];
    const float* scale = (const float*)d_in[10];
    const float* shift = (const float*)d_in[11];
    float* out = (float*)d_out;

    cudaFuncSetAttribute(mpnn_tc, cudaFuncAttributeMaxDynamicSharedMemorySize,
                         SMEM_BYTES);
    cudaFuncSetAttribute(sbias_kernel, cudaFuncAttributeMaxDynamicSharedMemorySize,
                         SB_SMEM);

    prep_weights<<<(4 * HH * HH + 255) / 256, 256>>>(
        (const float*)d_in[4], (const float*)d_in[6], (const float*)d_in[8]);
    sbias_kernel<<<NODES / 128, 128, SB_SMEM>>>(atom_encode, atom_mask, b0);
    mpnn_tc<<<NODES / 4, 128, SMEM_BYTES>>>(atom_encode, atom_mask, dist,
                                            edge_index, W0, b1, b2);
    stats_kernel<<<BB * HH, 256>>>(atom_mask);

    const int OUT0 = NODES * HH;
    norm_kernel<<<(OUT0 + 255) / 256, 256>>>(out, atom_mask, scale, shift);

    const int PT = NODES + 2 * NODES * KK;
    if (out_size >= OUT0 + PT) {
        passthru_kernel<<<(PT + 255) / 256, 256>>>(out + OUT0, atom_mask, dist,
                                                   edge_index);
    }
}

// round 9
// speedup vs baseline: 7.0936x; 1.8009x over previous
#include <cuda_runtime.h>
#include <cuda_fp16.h>
#include <cstdint>
#include <math.h>

#define BB 4
#define NN 4096
#define KK 32
#define HH 128
#define NODES (BB*NN)

// ---------------- scratch (static, no allocation) ----------------
__device__ float g_upd[NODES * HH];          // 8 MB
__device__ float g_sbias[NODES * HH];        // 8 MB: b0 + self@W0_self per node
__device__ float g_mean[BB * HH];
__device__ float g_rstd[BB * HH];
// stats partials: 32 chunks of 128 nodes per batch
__device__ float g_ps[BB * 32 * HH];
__device__ float g_pq[BB * 32 * HH];
__device__ float g_pc[BB * 32];
// prepped fp16 weights:
//   [0, 98304)       : layers 0..2, hi-only, 32 KB each (4 quarters x 8 KB, swizzled)
//   [98304, 163840)  : W0_self hi/lo, 4 quarters x (hi 8 KB | lo 8 KB)
__device__ __align__(16) unsigned char g_Wp[163840];

// ---------------- helpers ----------------
__device__ __forceinline__ uint32_t smem_u32(const void* p) {
    uint32_t a;
    asm("{ .reg .u64 t; cvta.to.shared.u64 t, %1; cvt.u32.u64 %0, t; }"
        : "=r"(a) : "l"(p));
    return a;
}
// fast GELU: tanh form with hardware tanh.approx (sm_75+), ~6 ops.
// |bias vs exact-erf gelu| ~1e-4 abs, below fp16 activation rounding.
__device__ __forceinline__ float gelu_fast(float x) {
    float x2 = x * x;
    float y  = x * fmaf(0.03567740814f, x2, 0.7978845608f);
    float t;
    asm("tanh.approx.f32 %0, %1;" : "=f"(t) : "f"(y));
    float h = 0.5f * x;
    return fmaf(h, t, h);
}
__device__ __forceinline__ uint32_t packh2(float x, float y) {
    __half2 h = __floats2half2_rn(x, y);
    return *(uint32_t*)&h;
}
__device__ __forceinline__ void ldm4(uint32_t* r, uint32_t addr) {
    asm volatile("ldmatrix.sync.aligned.m8n8.x4.shared.b16 {%0,%1,%2,%3}, [%4];"
        : "=r"(r[0]), "=r"(r[1]), "=r"(r[2]), "=r"(r[3]) : "r"(addr));
}
__device__ __forceinline__ void mma_f16(float* c, const uint32_t* a, const uint32_t* b) {
    asm volatile(
        "mma.sync.aligned.m16n8k16.row.col.f32.f16.f16.f32 "
        "{%0,%1,%2,%3}, {%4,%5,%6,%7}, {%8,%9}, {%0,%1,%2,%3};"
        : "+f"(c[0]), "+f"(c[1]), "+f"(c[2]), "+f"(c[3])
        : "r"(a[0]), "r"(a[1]), "r"(a[2]), "r"(a[3]), "r"(b[0]), "r"(b[1]));
}
#define CP_ASYNC16(dst, src) \
    asm volatile("cp.async.cg.shared.global [%0], [%1], 16;" \
        :: "r"(dst), "l"(src) : "memory")
#define CP_COMMIT() asm volatile("cp.async.commit_group;" ::: "memory")
#define CP_WAIT1()  asm volatile("cp.async.wait_group 1;" ::: "memory")
#define CP_WAIT0()  asm volatile("cp.async.wait_group 0;" ::: "memory")

// ---------------- prep: W -> fp16, swizzled, quartered ----------------
__global__ void prep_weights(const float* __restrict__ W0,
                             const float* __restrict__ W1,
                             const float* __restrict__ W2)
{
    int i = blockIdx.x * blockDim.x + threadIdx.x;
    if (i >= 4 * HH * HH) return;
    int lyr = i >> 14, r = i & 16383, n = r >> 7, k = r & 127;
    float v;
    if (lyr == 0)      v = W0[k * HH + n];            // src block rows 0..127
    else if (lyr == 1) v = W1[k * HH + n];
    else if (lyr == 2) v = W2[k * HH + n];
    else               v = W0[(HH + k) * HH + n];     // self block rows 128..255
    __half h = __float2half_rn(v);
    int q = n >> 5, nl = n & 31;
    int byte = nl * 256 + (((k >> 3) ^ (nl & 7)) << 4) + ((k & 7) << 1);
    if (lyr < 3) {
        *(__half*)(g_Wp + lyr * 32768 + q * 8192 + byte) = h;
    } else {
        __half lo = __float2half_rn(v - __half2float(h));
        unsigned char* base = g_Wp + 98304 + q * 16384;
        *(__half*)(base + byte)        = h;
        *(__half*)(base + 8192 + byte) = lo;
    }
}

// ---------------- self-bias mini-GEMM: g_sbias = b0 + self@W0_self ----------------
#define SB_SMEM 98304
__global__ __launch_bounds__(128)
void sbias_kernel(const float* __restrict__ enc, const float* __restrict__ mask,
                  const float* __restrict__ b0)
{
    extern __shared__ char smem[];
    uint32_t sb = smem_u32(smem);
    const int tid = threadIdx.x;
    const int w = tid >> 5, l = tid & 31;
    const int base_node = blockIdx.x << 7;

    // gather masked self rows into fp16 A plane
    {
        const int node = base_node + tid;
        const float mm = mask[node];
        const float4* rp = (const float4*)(enc + (size_t)node * HH);
        const int rp7 = tid & 7;
        #pragma unroll
        for (int c = 0; c < 16; c++) {
            float4 v0 = rp[2 * c], v1 = rp[2 * c + 1];
            uint32_t u0 = packh2(v0.x * mm, v0.y * mm);
            uint32_t u1 = packh2(v0.z * mm, v0.w * mm);
            uint32_t u2 = packh2(v1.x * mm, v1.y * mm);
            uint32_t u3 = packh2(v1.z * mm, v1.w * mm);
            uint32_t off = (uint32_t)tid * 256 + (uint32_t)((c ^ rp7) << 4);
            *(uint4*)(smem + off) = make_uint4(u0, u1, u2, u3);
        }
    }
    // stage full W0_self hi/lo: 64 KB at +32768
    {
        const uint4* src = (const uint4*)(g_Wp + 98304);
        uint4* dst = (uint4*)(smem + 32768);
        #pragma unroll
        for (int i = 0; i < 32; i++) dst[tid + 128 * i] = src[tid + 128 * i];
    }
    __syncthreads();

    const int rA0 = (w << 5) + (l & 15), rA1 = rA0 + 16;
    const uint32_t cselA = (uint32_t)(l >> 4);
    const uint32_t baseA0 = sb + (uint32_t)rA0 * 256;
    const uint32_t baseA1 = sb + (uint32_t)rA1 * 256;
    const uint32_t parA0 = (uint32_t)(rA0 & 7), parA1 = (uint32_t)(rA1 & 7);
    const int rB = (l & 7) + ((l >> 4) << 3);
    const uint32_t cselB = (uint32_t)((l >> 3) & 1);
    const uint32_t parB = (uint32_t)(rB & 7);
    const int c2 = (l & 3) << 1;

    float acc[2][16][4];
    #pragma unroll
    for (int nt = 0; nt < 16; nt++) {
        float bx = b0[8 * nt + c2], by = b0[8 * nt + c2 + 1];
        #pragma unroll
        for (int m = 0; m < 2; m++) {
            acc[m][nt][0] = bx; acc[m][nt][1] = by;
            acc[m][nt][2] = bx; acc[m][nt][3] = by;
        }
    }

    #pragma unroll
    for (int q = 0; q < 4; q++) {
        const uint32_t baseBq = sb + 32768 + (uint32_t)q * 16384 + (uint32_t)rB * 256;
        #pragma unroll
        for (int ks = 0; ks < 8; ks++) {
            uint32_t ah0[4], ah1[4], bh[2][4], bl[2][4];
            const uint32_t kA = (uint32_t)(2 * ks) + cselA;
            const uint32_t kB = (uint32_t)(2 * ks) + cselB;
            ldm4(ah0, baseA0 + ((kA ^ parA0) << 4));
            ldm4(ah1, baseA1 + ((kA ^ parA1) << 4));
            #pragma unroll
            for (int jj = 0; jj < 2; jj++) {
                ldm4(bh[jj], baseBq + jj * 4096 + ((kB ^ parB) << 4));
                ldm4(bl[jj], baseBq + 8192 + jj * 4096 + ((kB ^ parB) << 4));
            }
            #pragma unroll
            for (int tt = 0; tt < 4; tt++) {
                const int nt = 4 * q + tt;
                const uint32_t* bH = &bh[tt >> 1][(tt & 1) << 1];
                const uint32_t* bL = &bl[tt >> 1][(tt & 1) << 1];
                mma_f16(acc[0][nt], ah0, bH);
                mma_f16(acc[1][nt], ah1, bH);
                mma_f16(acc[0][nt], ah0, bL);
                mma_f16(acc[1][nt], ah1, bL);
            }
        }
    }

    #pragma unroll
    for (int m = 0; m < 2; m++) {
        const int row0 = base_node + (w << 5) + (m << 4) + (l >> 2);
        #pragma unroll
        for (int nt = 0; nt < 16; nt++) {
            *(float2*)&g_sbias[(size_t)row0 * HH + 8 * nt + c2] =
                make_float2(acc[m][nt][0], acc[m][nt][1]);
            *(float2*)&g_sbias[(size_t)(row0 + 8) * HH + 8 * nt + c2] =
                make_float2(acc[m][nt][2], acc[m][nt][3]);
        }
    }
}

// ---------------- main fused kernel (128 threads; hi-only, full-layer staging) ----
// smem layout (bytes)
#define OFF_A     0        // 32768 : A fp16 plane, 128 rows x 256B, chunk-swizzled
#define OFF_B     32768    // 65536 : double-buffered full-layer weights (2 x 32 KB)
#define OFF_SELF  98304    // 2048
#define OFF_SBIAS 100352   // 2048
#define OFF_MSUM  102400   // 2048 : [4 warps][128]
#define OFF_W256  104448   // 512
#define OFF_BV    104960   // 1024
#define OFF_DE    105984   // 512
#define OFF_VLD   106496   // 512
#define OFF_INV   107008   // 16
#define OFF_NM    107024   // 16
#define SMEM_BYTES 107040

__global__ __launch_bounds__(128)
void mpnn_tc(const float* __restrict__ enc, const float* __restrict__ mask,
             const float* __restrict__ dist, const int* __restrict__ eidx,
             const float* __restrict__ W0,
             const float* __restrict__ b1, const float* __restrict__ b2)
{
    extern __shared__ char smem[];
    uint32_t sb = smem_u32(smem);
    float* smf = (float*)smem;
    const int tid = threadIdx.x;
    const int w = tid >> 5, l = tid & 31;
    const int base_node = blockIdx.x << 2;
    const int batch = base_node >> 12;

    // prologue: prefetch layer-0 weights (32 KB) immediately
    {
        const char* src = (const char*)g_Wp + tid * 16;
        uint32_t dst = sb + OFF_B + tid * 16;
        #pragma unroll
        for (int i = 0; i < 16; i++)
            CP_ASYNC16(dst + i * 2048, src + i * 2048);
        CP_COMMIT();
    }

    // ---- per-edge metadata (thread = edge row) ----
    const int ei = eidx[base_node * KK + tid];
    const int gsrc = batch * NN + ((ei < 0) ? 0 : ei);
    const float smask = mask[gsrc];
    smf[(OFF_DE  >> 2) + tid] = dist[base_node * KK + tid];
    smf[(OFF_VLD >> 2) + tid] = (ei >= 0) ? 1.0f : 0.0f;
    unsigned cnt = __reduce_add_sync(0xffffffffu, (ei >= 0) ? 1u : 0u);
    if (l == 0) smf[(OFF_INV >> 2) + w] = 1.0f / ((cnt == 0) ? 1.0f : (float)cnt);

    #pragma unroll
    for (int g = 0; g < 4; g++) {
        float mm = mask[base_node + g];
        smf[(OFF_SELF  >> 2) + g * HH + tid] =
            enc[(size_t)(base_node + g) * HH + tid] * mm;
        smf[(OFF_SBIAS >> 2) + g * HH + tid] =
            g_sbias[(size_t)(base_node + g) * HH + tid];
    }
    if (tid < 4) smf[(OFF_NM >> 2) + tid] = mask[base_node + tid];
    smf[(OFF_W256 >> 2) + tid]      = W0[256 * HH + tid];
    smf[(OFF_BV   >> 2) + tid]      = b1[tid];
    smf[(OFF_BV   >> 2) + HH + tid] = b2[tid];

    // ---- gather neighbor features -> A plane (fp16, swizzled) ----
    {
        const float4* rp = (const float4*)(enc + (size_t)gsrc * HH);
        const int rp7 = tid & 7;
        #pragma unroll
        for (int c = 0; c < 16; c++) {
            float4 v0 = rp[2 * c], v1 = rp[2 * c + 1];
            uint32_t u0 = packh2(v0.x * smask, v0.y * smask);
            uint32_t u1 = packh2(v0.z * smask, v0.w * smask);
            uint32_t u2 = packh2(v1.x * smask, v1.y * smask);
            uint32_t u3 = packh2(v1.z * smask, v1.w * smask);
            uint32_t off = (uint32_t)tid * 256 + (uint32_t)((c ^ rp7) << 4);
            *(uint4*)(smem + OFF_A + off) = make_uint4(u0, u1, u2, u3);
        }
    }

    // ---- lane constants for ldmatrix addressing ----
    const int rA0 = (w << 5) + (l & 15), rA1 = rA0 + 16;
    const uint32_t cselA = (uint32_t)(l >> 4);
    const uint32_t baseA0 = sb + OFF_A + (uint32_t)rA0 * 256;
    const uint32_t baseA1 = sb + OFF_A + (uint32_t)rA1 * 256;
    const uint32_t parA0 = (uint32_t)(rA0 & 7), parA1 = (uint32_t)(rA1 & 7);
    const int rB = (l & 7) + ((l >> 4) << 3);
    const uint32_t cselB = (uint32_t)((l >> 3) & 1);
    const uint32_t parB = (uint32_t)(rB & 7);
    const int c2 = (l & 3) << 1;

    float de4[4], vl4[4];
    #pragma unroll
    for (int ri = 0; ri < 4; ri++) {
        int rr = (w << 5) + (l >> 2) + 8 * ri;
        de4[ri] = smf[(OFF_DE  >> 2) + rr];
        vl4[ri] = smf[(OFF_VLD >> 2) + rr];
    }
    __syncthreads();   // A plane + small tables visible

    float acc[2][16][4];

    #pragma unroll 1
    for (int layer = 0; layer < 3; layer++) {
        // ---- init acc with bias ----
        if (layer == 0) {
            #pragma unroll
            for (int nt = 0; nt < 16; nt++) {
                float2 sb2 = *(float2*)&smf[(OFF_SBIAS >> 2) + w * HH + 8 * nt + c2];
                float2 w2  = *(float2*)&smf[(OFF_W256  >> 2) + 8 * nt + c2];
                #pragma unroll
                for (int m = 0; m < 2; m++) {
                    acc[m][nt][0] = fmaf(de4[2 * m],     w2.x, sb2.x);
                    acc[m][nt][1] = fmaf(de4[2 * m],     w2.y, sb2.y);
                    acc[m][nt][2] = fmaf(de4[2 * m + 1], w2.x, sb2.x);
                    acc[m][nt][3] = fmaf(de4[2 * m + 1], w2.y, sb2.y);
                }
            }
        } else {
            const float* bv = &smf[(OFF_BV >> 2) + (layer - 1) * HH];
            #pragma unroll
            for (int nt = 0; nt < 16; nt++) {
                float2 b2v = *(float2*)&bv[8 * nt + c2];
                #pragma unroll
                for (int m = 0; m < 2; m++) {
                    acc[m][nt][0] = b2v.x; acc[m][nt][1] = b2v.y;
                    acc[m][nt][2] = b2v.x; acc[m][nt][3] = b2v.y;
                }
            }
        }

        // ---- prefetch next layer's weights; wait for current ----
        if (layer + 1 < 3) {
            const char* src = (const char*)g_Wp + (layer + 1) * 32768 + tid * 16;
            uint32_t dst = sb + OFF_B + ((layer + 1) & 1) * 32768 + tid * 16;
            #pragma unroll
            for (int i = 0; i < 16; i++)
                CP_ASYNC16(dst + i * 2048, src + i * 2048);
            CP_COMMIT();
            CP_WAIT1();
        } else {
            CP_WAIT0();
        }
        __syncthreads();   // current layer weights visible to all warps

        // ---- full layer: 4 quarters x 8 k-steps, hi product only ----
        const uint32_t baseBL = sb + OFF_B + (uint32_t)((layer & 1) * 32768)
                              + (uint32_t)rB * 256;
        #pragma unroll
        for (int q = 0; q < 4; q++) {
            const uint32_t baseBq = baseBL + (uint32_t)q * 8192;
            #pragma unroll
            for (int ks = 0; ks < 8; ks++) {
                uint32_t ah0[4], ah1[4], bh[2][4];
                const uint32_t kA = (uint32_t)(2 * ks) + cselA;
                const uint32_t kB = (uint32_t)(2 * ks) + cselB;
                ldm4(ah0, baseA0 + ((kA ^ parA0) << 4));
                ldm4(ah1, baseA1 + ((kA ^ parA1) << 4));
                #pragma unroll
                for (int jj = 0; jj < 2; jj++)
                    ldm4(bh[jj], baseBq + jj * 4096 + ((kB ^ parB) << 4));
                #pragma unroll
                for (int tt = 0; tt < 4; tt++) {
                    const int nt = 4 * q + tt;
                    const uint32_t* bH = &bh[tt >> 1][(tt & 1) << 1];
                    mma_f16(acc[0][nt], ah0, bH);
                    mma_f16(acc[1][nt], ah1, bH);
                }
            }
        }
        __syncthreads();   // all warps done with A + this weight buffer

        if (layer < 2) {
            // ---- epilogue: gelu -> A plane (fp16, swizzled) ----
            const int r0 = (w << 5) + (l >> 2);
            #pragma unroll
            for (int m = 0; m < 2; m++) {
                const int ra = r0 + 16 * m, rb = ra + 8;
                const uint32_t sa  = (uint32_t)ra * 256 + (uint32_t)((l & 3) << 2);
                const uint32_t sbt = (uint32_t)rb * 256 + (uint32_t)((l & 3) << 2);
                #pragma unroll
                for (int nt = 0; nt < 16; nt++) {
                    uint32_t hA = packh2(gelu_fast(acc[m][nt][0]),
                                         gelu_fast(acc[m][nt][1]));
                    uint32_t hB = packh2(gelu_fast(acc[m][nt][2]),
                                         gelu_fast(acc[m][nt][3]));
                    uint32_t oa = sa  + (uint32_t)((nt ^ (ra & 7)) << 4);
                    uint32_t ob = sbt + (uint32_t)((nt ^ (rb & 7)) << 4);
                    *(uint32_t*)(smem + OFF_A + oa) = hA;
                    *(uint32_t*)(smem + OFF_A + ob) = hB;
                }
            }
            __syncthreads();
        } else {
            // ---- final: gelu*valid, reduce 32 edges -> per-node msum ----
            #pragma unroll
            for (int nt = 0; nt < 16; nt++) {
                float s0 = gelu_fast(acc[0][nt][0]) * vl4[0]
                         + gelu_fast(acc[0][nt][2]) * vl4[1]
                         + gelu_fast(acc[1][nt][0]) * vl4[2]
                         + gelu_fast(acc[1][nt][2]) * vl4[3];
                float s1 = gelu_fast(acc[0][nt][1]) * vl4[0]
                         + gelu_fast(acc[0][nt][3]) * vl4[1]
                         + gelu_fast(acc[1][nt][1]) * vl4[2]
                         + gelu_fast(acc[1][nt][3]) * vl4[3];
                #pragma unroll
                for (int sh = 4; sh < 32; sh <<= 1) {
                    s0 += __shfl_xor_sync(0xffffffffu, s0, sh);
                    s1 += __shfl_xor_sync(0xffffffffu, s1, sh);
                }
                if (l < 4) {
                    smf[(OFF_MSUM >> 2) + w * HH + 8 * nt + c2]     = s0;
                    smf[(OFF_MSUM >> 2) + w * HH + 8 * nt + c2 + 1] = s1;
                }
            }
            __syncthreads();
            #pragma unroll
            for (int g = 0; g < 4; g++) {
                float ms  = smf[(OFF_MSUM >> 2) + g * HH + tid];
                float upd = smf[(OFF_SELF >> 2) + g * HH + tid]
                          + ms * smf[(OFF_INV >> 2) + g] * smf[(OFF_NM >> 2) + g];
                g_upd[(size_t)(base_node + g) * HH + tid] = upd;
            }
        }
    }
}

// ---------------- graph norm: two-stage coalesced stats ----------------
// stage A: 128 blocks, each sums a contiguous 128-node chunk (coalesced rows)
__global__ __launch_bounds__(256)
void stats_a(const float* __restrict__ atom_mask)
{
    const int blk = blockIdx.x;
    const int b = blk >> 5, chunk = blk & 31;
    const int t = threadIdx.x;
    const int half = t >> 7, col = t & 127;
    const float* base = g_upd + ((size_t)(b * NN) + chunk * 128) * HH;

    // count valid nodes in chunk (threads 0..127, warps 0..3)
    float c = (t < 128) ? atom_mask[b * NN + chunk * 128 + t] : 0.0f;
    #pragma unroll
    for (int sh = 16; sh > 0; sh >>= 1)
        c += __shfl_xor_sync(0xffffffffu, c, sh);
    __shared__ float sc[8];
    if ((t & 31) == 0) sc[t >> 5] = c;

    float s = 0.0f, q = 0.0f;
    #pragma unroll 4
    for (int i = 0; i < 64; i++) {
        float v = base[(2 * i + half) * HH + col];
        s += v; q = fmaf(v, v, q);
    }
    __shared__ float ss[256], sq[256];
    ss[t] = s; sq[t] = q;
    __syncthreads();
    if (t < 128) {
        g_ps[(b * 32 + chunk) * HH + t] = ss[t] + ss[t + 128];
        g_pq[(b * 32 + chunk) * HH + t] = sq[t] + sq[t + 128];
    }
    if (t == 0)
        g_pc[b * 32 + chunk] = sc[0] + sc[1] + sc[2] + sc[3];
}

// stage B: one block combines 32 partials per (b,h)
__global__ __launch_bounds__(512)
void stats_b()
{
    const int t = threadIdx.x;          // t = b*128 + h
    const int b = t >> 7, h = t & 127;
    float s = 0.0f, q = 0.0f, c = 0.0f;
    #pragma unroll 8
    for (int ch = 0; ch < 32; ch++) {
        s += g_ps[(b * 32 + ch) * HH + h];
        q += g_pq[(b * 32 + ch) * HH + h];
        c += g_pc[b * 32 + ch];
    }
    if (c == 0.0f) c = 1.0f;
    float mean = s / c;
    float var = (q - 2.0f * mean * s + (float)NN * mean * mean) / c;
    g_mean[t] = mean;
    g_rstd[t] = rsqrtf(var + 1e-5f);
}

__global__ __launch_bounds__(256)
void norm_kernel(float* __restrict__ out,
                 const float* __restrict__ atom_mask,
                 const float* __restrict__ scale,
                 const float* __restrict__ shift)
{
    const int i = blockIdx.x * 256 + threadIdx.x;
    if (i >= NODES * HH) return;
    const int h  = i & (HH - 1);
    const int bn = i >> 7;
    const int b  = bn >> 12;
    const float v = g_upd[i];
    out[i] = ((v - g_mean[b * HH + h]) * g_rstd[b * HH + h] * scale[h] + shift[h])
             * atom_mask[bn];
}

__global__ __launch_bounds__(256)
void passthru_kernel(float* __restrict__ out,
                     const float* __restrict__ atom_mask,
                     const float* __restrict__ dist,
                     const int*   __restrict__ edge)
{
    const int M0 = NODES;
    const int M1 = NODES * KK;
    const int total = M0 + 2 * M1;
    const int i = blockIdx.x * 256 + threadIdx.x;
    if (i >= total) return;
    if (i < M0)            out[i] = atom_mask[i];
    else if (i < M0 + M1)  out[i] = dist[i - M0];
    else                   out[i] = (float)edge[i - M0 - M1];
}

extern "C" void kernel_launch(void* const* d_in, const int* in_sizes, int n_in,
                              void* d_out, int out_size)
{
    const float* atom_encode = (const float*)d_in[0];
    const float* atom_mask   = (const float*)d_in[1];
    const float* dist        = (const float*)d_in[2];
    const int*   edge_index  = (const int*)  d_in[3];
    const float* W0 = (const float*)d_in[4];
    const float* b0 = (const float*)d_in[5];
    const float* b1 = (const float*)d_in[7];
    const float* b2 = (const float*)d_in[9];
    const float* scale = (const float*)d_in[10];
    const float* shift = (const float*)d_in[11];
    float* out = (float*)d_out;

    cudaFuncSetAttribute(mpnn_tc, cudaFuncAttributeMaxDynamicSharedMemorySize,
                         SMEM_BYTES);
    cudaFuncSetAttribute(sbias_kernel, cudaFuncAttributeMaxDynamicSharedMemorySize,
                         SB_SMEM);

    prep_weights<<<(4 * HH * HH + 255) / 256, 256>>>(
        (const float*)d_in[4], (const float*)d_in[6], (const float*)d_in[8]);
    sbias_kernel<<<NODES / 128, 128, SB_SMEM>>>(atom_encode, atom_mask, b0);
    mpnn_tc<<<NODES / 4, 128, SMEM_BYTES>>>(atom_encode, atom_mask, dist,
                                            edge_index, W0, b1, b2);
    stats_a<<<BB * 32, 256>>>(atom_mask);
    stats_b<<<1, 512>>>();

    const int OUT0 = NODES * HH;
    norm_kernel<<<(OUT0 + 255) / 256, 256>>>(out, atom_mask, scale, shift);

    const int PT = NODES + 2 * NODES * KK;
    if (out_size >= OUT0 + PT) {
        passthru_kernel<<<(PT + 255) / 256, 256>>>(out + OUT0, atom_mask, dist,
                                                   edge_index);
    }
}

// round 12
// speedup vs baseline: 7.2334x; 1.0197x over previous
#include <cuda_runtime.h>
#include <cuda_fp16.h>
#include <cstdint>
#include <math.h>

#define BB 4
#define NN 4096
#define KK 32
#define HH 128
#define NODES (BB*NN)

// ---------------- scratch (static, no allocation) ----------------
__device__ float g_upd[NODES * HH];          // 8 MB
__device__ float g_sbias[NODES * HH];        // 8 MB: b0 + self@W0_self per node
__device__ float g_mean[BB * HH];
__device__ float g_rstd[BB * HH];
// stats partials: 32 chunks of 128 nodes per batch
__device__ float g_ps[BB * 32 * HH];
__device__ float g_pq[BB * 32 * HH];
__device__ float g_pc[BB * 32];
// prepped fp16 weights:
//   [0, 98304)       : layers 0..2, hi-only, 32 KB each (4 quarters x 8 KB, swizzled)
//   [98304, 163840)  : W0_self hi/lo, 4 quarters x (hi 8 KB | lo 8 KB)
__device__ __align__(16) unsigned char g_Wp[163840];

// ---------------- helpers ----------------
__device__ __forceinline__ uint32_t smem_u32(const void* p) {
    uint32_t a;
    asm("{ .reg .u64 t; cvta.to.shared.u64 t, %1; cvt.u32.u64 %0, t; }"
        : "=r"(a) : "l"(p));
    return a;
}
// fast GELU: tanh form with hardware tanh.approx (sm_75+), ~6 ops.
__device__ __forceinline__ float gelu_fast(float x) {
    float x2 = x * x;
    float y  = x * fmaf(0.03567740814f, x2, 0.7978845608f);
    float t;
    asm("tanh.approx.f32 %0, %1;" : "=f"(t) : "f"(y));
    float h = 0.5f * x;
    return fmaf(h, t, h);
}
__device__ __forceinline__ uint32_t packh2(float x, float y) {
    __half2 h = __floats2half2_rn(x, y);
    return *(uint32_t*)&h;
}
__device__ __forceinline__ void ldm4(uint32_t* r, uint32_t addr) {
    asm volatile("ldmatrix.sync.aligned.m8n8.x4.shared.b16 {%0,%1,%2,%3}, [%4];"
        : "=r"(r[0]), "=r"(r[1]), "=r"(r[2]), "=r"(r[3]) : "r"(addr));
}
__device__ __forceinline__ void mma_f16(float* c, const uint32_t* a, const uint32_t* b) {
    asm volatile(
        "mma.sync.aligned.m16n8k16.row.col.f32.f16.f16.f32 "
        "{%0,%1,%2,%3}, {%4,%5,%6,%7}, {%8,%9}, {%0,%1,%2,%3};"
        : "+f"(c[0]), "+f"(c[1]), "+f"(c[2]), "+f"(c[3])
        : "r"(a[0]), "r"(a[1]), "r"(a[2]), "r"(a[3]), "r"(b[0]), "r"(b[1]));
}
#define CP_ASYNC16(dst, src) \
    asm volatile("cp.async.cg.shared.global [%0], [%1], 16;" \
        :: "r"(dst), "l"(src) : "memory")
#define CP_COMMIT() asm volatile("cp.async.commit_group;" ::: "memory")
#define CP_WAIT1()  asm volatile("cp.async.wait_group 1;" ::: "memory")
#define CP_WAIT0()  asm volatile("cp.async.wait_group 0;" ::: "memory")

// ---------------- prep: W -> fp16, swizzled, quartered ----------------
__global__ void prep_weights(const float* __restrict__ W0,
                             const float* __restrict__ W1,
                             const float* __restrict__ W2)
{
    int i = blockIdx.x * blockDim.x + threadIdx.x;
    if (i >= 4 * HH * HH) return;
    int lyr = i >> 14, r = i & 16383, n = r >> 7, k = r & 127;
    float v;
    if (lyr == 0)      v = W0[k * HH + n];            // src block rows 0..127
    else if (lyr == 1) v = W1[k * HH + n];
    else if (lyr == 2) v = W2[k * HH + n];
    else               v = W0[(HH + k) * HH + n];     // self block rows 128..255
    __half h = __float2half_rn(v);
    int q = n >> 5, nl = n & 31;
    int byte = nl * 256 + (((k >> 3) ^ (nl & 7)) << 4) + ((k & 7) << 1);
    if (lyr < 3) {
        *(__half*)(g_Wp + lyr * 32768 + q * 8192 + byte) = h;
    } else {
        __half lo = __float2half_rn(v - __half2float(h));
        unsigned char* base = g_Wp + 98304 + q * 16384;
        *(__half*)(base + byte)        = h;
        *(__half*)(base + 8192 + byte) = lo;
    }
}

// ---------------- self-bias mini-GEMM: g_sbias = b0 + self@W0_self ----------------
#define SB_SMEM 98304
__global__ __launch_bounds__(128)
void sbias_kernel(const float* __restrict__ enc, const float* __restrict__ mask,
                  const float* __restrict__ b0)
{
    extern __shared__ char smem[];
    uint32_t sb = smem_u32(smem);
    const int tid = threadIdx.x;
    const int w = tid >> 5, l = tid & 31;
    const int base_node = blockIdx.x << 7;

    // gather masked self rows into fp16 A plane
    {
        const int node = base_node + tid;
        const float mm = mask[node];
        const float4* rp = (const float4*)(enc + (size_t)node * HH);
        const int rp7 = tid & 7;
        #pragma unroll
        for (int c = 0; c < 16; c++) {
            float4 v0 = rp[2 * c], v1 = rp[2 * c + 1];
            uint32_t u0 = packh2(v0.x * mm, v0.y * mm);
            uint32_t u1 = packh2(v0.z * mm, v0.w * mm);
            uint32_t u2 = packh2(v1.x * mm, v1.y * mm);
            uint32_t u3 = packh2(v1.z * mm, v1.w * mm);
            uint32_t off = (uint32_t)tid * 256 + (uint32_t)((c ^ rp7) << 4);
            *(uint4*)(smem + off) = make_uint4(u0, u1, u2, u3);
        }
    }
    // stage full W0_self hi/lo: 64 KB at +32768
    {
        const uint4* src = (const uint4*)(g_Wp + 98304);
        uint4* dst = (uint4*)(smem + 32768);
        #pragma unroll
        for (int i = 0; i < 32; i++) dst[tid + 128 * i] = src[tid + 128 * i];
    }
    __syncthreads();

    const int rA0 = (w << 5) + (l & 15), rA1 = rA0 + 16;
    const uint32_t cselA = (uint32_t)(l >> 4);
    const uint32_t baseA0 = sb + (uint32_t)rA0 * 256;
    const uint32_t baseA1 = sb + (uint32_t)rA1 * 256;
    const uint32_t parA0 = (uint32_t)(rA0 & 7), parA1 = (uint32_t)(rA1 & 7);
    const int rB = (l & 7) + ((l >> 4) << 3);
    const uint32_t cselB = (uint32_t)((l >> 3) & 1);
    const uint32_t parB = (uint32_t)(rB & 7);
    const int c2 = (l & 3) << 1;

    float acc[2][16][4];
    #pragma unroll
    for (int nt = 0; nt < 16; nt++) {
        float bx = b0[8 * nt + c2], by = b0[8 * nt + c2 + 1];
        #pragma unroll
        for (int m = 0; m < 2; m++) {
            acc[m][nt][0] = bx; acc[m][nt][1] = by;
            acc[m][nt][2] = bx; acc[m][nt][3] = by;
        }
    }

    #pragma unroll
    for (int q = 0; q < 4; q++) {
        const uint32_t baseBq = sb + 32768 + (uint32_t)q * 16384 + (uint32_t)rB * 256;
        #pragma unroll
        for (int ks = 0; ks < 8; ks++) {
            uint32_t ah0[4], ah1[4], bh[2][4], bl[2][4];
            const uint32_t kA = (uint32_t)(2 * ks) + cselA;
            const uint32_t kB = (uint32_t)(2 * ks) + cselB;
            ldm4(ah0, baseA0 + ((kA ^ parA0) << 4));
            ldm4(ah1, baseA1 + ((kA ^ parA1) << 4));
            #pragma unroll
            for (int jj = 0; jj < 2; jj++) {
                ldm4(bh[jj], baseBq + jj * 4096 + ((kB ^ parB) << 4));
                ldm4(bl[jj], baseBq + 8192 + jj * 4096 + ((kB ^ parB) << 4));
            }
            #pragma unroll
            for (int tt = 0; tt < 4; tt++) {
                const int nt = 4 * q + tt;
                const uint32_t* bH = &bh[tt >> 1][(tt & 1) << 1];
                const uint32_t* bL = &bl[tt >> 1][(tt & 1) << 1];
                mma_f16(acc[0][nt], ah0, bH);
                mma_f16(acc[1][nt], ah1, bH);
                mma_f16(acc[0][nt], ah0, bL);
                mma_f16(acc[1][nt], ah1, bL);
            }
        }
    }

    #pragma unroll
    for (int m = 0; m < 2; m++) {
        const int row0 = base_node + (w << 5) + (m << 4) + (l >> 2);
        #pragma unroll
        for (int nt = 0; nt < 16; nt++) {
            *(float2*)&g_sbias[(size_t)row0 * HH + 8 * nt + c2] =
                make_float2(acc[m][nt][0], acc[m][nt][1]);
            *(float2*)&g_sbias[(size_t)(row0 + 8) * HH + 8 * nt + c2] =
                make_float2(acc[m][nt][2], acc[m][nt][3]);
        }
    }
}

// ---------------- main fused kernel (128 threads; hi-only, ks-outer mainloop) ----
// smem layout (bytes)
#define OFF_A     0        // 32768 : A fp16 plane, 128 rows x 256B, chunk-swizzled
#define OFF_B     32768    // 65536 : double-buffered full-layer weights (2 x 32 KB)
#define OFF_SELF  98304    // 2048
#define OFF_SBIAS 100352   // 2048
#define OFF_MSUM  102400   // 2048 : [4 warps][128]
#define OFF_W256  104448   // 512
#define OFF_BV    104960   // 1024
#define OFF_DE    105984   // 512
#define OFF_VLD   106496   // 512
#define OFF_INV   107008   // 16
#define OFF_NM    107024   // 16
#define SMEM_BYTES 107040

__global__ __launch_bounds__(128)
void mpnn_tc(const float* __restrict__ enc, const float* __restrict__ mask,
             const float* __restrict__ dist, const int* __restrict__ eidx,
             const float* __restrict__ W0,
             const float* __restrict__ b1, const float* __restrict__ b2)
{
    extern __shared__ char smem[];
    uint32_t sb = smem_u32(smem);
    float* smf = (float*)smem;
    const int tid = threadIdx.x;
    const int w = tid >> 5, l = tid & 31;
    const int base_node = blockIdx.x << 2;
    const int batch = base_node >> 12;

    // prologue: prefetch layer-0 weights (32 KB) immediately
    {
        const char* src = (const char*)g_Wp + tid * 16;
        uint32_t dst = sb + OFF_B + tid * 16;
        #pragma unroll
        for (int i = 0; i < 16; i++)
            CP_ASYNC16(dst + i * 2048, src + i * 2048);
        CP_COMMIT();
    }

    // ---- per-edge metadata (thread = edge row) ----
    const int ei = eidx[base_node * KK + tid];
    const int gsrc = batch * NN + ((ei < 0) ? 0 : ei);
    const float smask = mask[gsrc];
    smf[(OFF_DE  >> 2) + tid] = dist[base_node * KK + tid];
    smf[(OFF_VLD >> 2) + tid] = (ei >= 0) ? 1.0f : 0.0f;
    unsigned cnt = __reduce_add_sync(0xffffffffu, (ei >= 0) ? 1u : 0u);
    if (l == 0) smf[(OFF_INV >> 2) + w] = 1.0f / ((cnt == 0) ? 1.0f : (float)cnt);

    #pragma unroll
    for (int g = 0; g < 4; g++) {
        float mm = mask[base_node + g];
        smf[(OFF_SELF  >> 2) + g * HH + tid] =
            enc[(size_t)(base_node + g) * HH + tid] * mm;
        smf[(OFF_SBIAS >> 2) + g * HH + tid] =
            g_sbias[(size_t)(base_node + g) * HH + tid];
    }
    if (tid < 4) smf[(OFF_NM >> 2) + tid] = mask[base_node + tid];
    smf[(OFF_W256 >> 2) + tid]      = W0[256 * HH + tid];
    smf[(OFF_BV   >> 2) + tid]      = b1[tid];
    smf[(OFF_BV   >> 2) + HH + tid] = b2[tid];

    // ---- gather neighbor features -> A plane (fp16, swizzled) ----
    {
        const float4* rp = (const float4*)(enc + (size_t)gsrc * HH);
        const int rp7 = tid & 7;
        #pragma unroll
        for (int c = 0; c < 16; c++) {
            float4 v0 = rp[2 * c], v1 = rp[2 * c + 1];
            uint32_t u0 = packh2(v0.x * smask, v0.y * smask);
            uint32_t u1 = packh2(v0.z * smask, v0.w * smask);
            uint32_t u2 = packh2(v1.x * smask, v1.y * smask);
            uint32_t u3 = packh2(v1.z * smask, v1.w * smask);
            uint32_t off = (uint32_t)tid * 256 + (uint32_t)((c ^ rp7) << 4);
            *(uint4*)(smem + OFF_A + off) = make_uint4(u0, u1, u2, u3);
        }
    }

    // ---- lane constants for ldmatrix addressing ----
    const int rA0 = (w << 5) + (l & 15), rA1 = rA0 + 16;
    const uint32_t cselA = (uint32_t)(l >> 4);
    const uint32_t baseA0 = sb + OFF_A + (uint32_t)rA0 * 256;
    const uint32_t baseA1 = sb + OFF_A + (uint32_t)rA1 * 256;
    const uint32_t parA0 = (uint32_t)(rA0 & 7), parA1 = (uint32_t)(rA1 & 7);
    const int rB = (l & 7) + ((l >> 4) << 3);
    const uint32_t cselB = (uint32_t)((l >> 3) & 1);
    const uint32_t parB = (uint32_t)(rB & 7);
    const int c2 = (l & 3) << 1;

    float de4[4], vl4[4];
    #pragma unroll
    for (int ri = 0; ri < 4; ri++) {
        int rr = (w << 5) + (l >> 2) + 8 * ri;
        de4[ri] = smf[(OFF_DE  >> 2) + rr];
        vl4[ri] = smf[(OFF_VLD >> 2) + rr];
    }
    __syncthreads();   // A plane + small tables visible

    float acc[2][16][4];

    #pragma unroll 1
    for (int layer = 0; layer < 3; layer++) {
        // ---- init acc with bias ----
        if (layer == 0) {
            #pragma unroll
            for (int nt = 0; nt < 16; nt++) {
                float2 sb2 = *(float2*)&smf[(OFF_SBIAS >> 2) + w * HH + 8 * nt + c2];
                float2 w2  = *(float2*)&smf[(OFF_W256  >> 2) + 8 * nt + c2];
                #pragma unroll
                for (int m = 0; m < 2; m++) {
                    acc[m][nt][0] = fmaf(de4[2 * m],     w2.x, sb2.x);
                    acc[m][nt][1] = fmaf(de4[2 * m],     w2.y, sb2.y);
                    acc[m][nt][2] = fmaf(de4[2 * m + 1], w2.x, sb2.x);
                    acc[m][nt][3] = fmaf(de4[2 * m + 1], w2.y, sb2.y);
                }
            }
        } else {
            const float* bv = &smf[(OFF_BV >> 2) + (layer - 1) * HH];
            #pragma unroll
            for (int nt = 0; nt < 16; nt++) {
                float2 b2v = *(float2*)&bv[8 * nt + c2];
                #pragma unroll
                for (int m = 0; m < 2; m++) {
                    acc[m][nt][0] = b2v.x; acc[m][nt][1] = b2v.y;
                    acc[m][nt][2] = b2v.x; acc[m][nt][3] = b2v.y;
                }
            }
        }

        // ---- prefetch next layer's weights; wait for current ----
        if (layer + 1 < 3) {
            const char* src = (const char*)g_Wp + (layer + 1) * 32768 + tid * 16;
            uint32_t dst = sb + OFF_B + ((layer + 1) & 1) * 32768 + tid * 16;
            #pragma unroll
            for (int i = 0; i < 16; i++)
                CP_ASYNC16(dst + i * 2048, src + i * 2048);
            CP_COMMIT();
            CP_WAIT1();
        } else {
            CP_WAIT0();
        }
        __syncthreads();   // current layer weights visible to all warps

        // ---- full layer: ks-outer (A fragments hoisted), q-inner ----
        const uint32_t baseBL = sb + OFF_B + (uint32_t)((layer & 1) * 32768)
                              + (uint32_t)rB * 256;
        #pragma unroll
        for (int ks = 0; ks < 8; ks++) {
            uint32_t ah0[4], ah1[4];
            const uint32_t kA = (uint32_t)(2 * ks) + cselA;
            const uint32_t kB = (uint32_t)(2 * ks) + cselB;
            ldm4(ah0, baseA0 + ((kA ^ parA0) << 4));
            ldm4(ah1, baseA1 + ((kA ^ parA1) << 4));
            #pragma unroll
            for (int q = 0; q < 4; q++) {
                uint32_t bh[2][4];
                const uint32_t baseBq = baseBL + (uint32_t)q * 8192;
                #pragma unroll
                for (int jj = 0; jj < 2; jj++)
                    ldm4(bh[jj], baseBq + jj * 4096 + ((kB ^ parB) << 4));
                #pragma unroll
                for (int tt = 0; tt < 4; tt++) {
                    const int nt = 4 * q + tt;
                    const uint32_t* bH = &bh[tt >> 1][(tt & 1) << 1];
                    mma_f16(acc[0][nt], ah0, bH);
                    mma_f16(acc[1][nt], ah1, bH);
                }
            }
        }
        __syncthreads();   // all warps done with A + this weight buffer

        if (layer < 2) {
            // ---- epilogue: gelu -> A plane (fp16, swizzled) ----
            const int r0 = (w << 5) + (l >> 2);
            #pragma unroll
            for (int m = 0; m < 2; m++) {
                const int ra = r0 + 16 * m, rb = ra + 8;
                const uint32_t sa  = (uint32_t)ra * 256 + (uint32_t)((l & 3) << 2);
                const uint32_t sbt = (uint32_t)rb * 256 + (uint32_t)((l & 3) << 2);
                #pragma unroll
                for (int nt = 0; nt < 16; nt++) {
                    uint32_t hA = packh2(gelu_fast(acc[m][nt][0]),
                                         gelu_fast(acc[m][nt][1]));
                    uint32_t hB = packh2(gelu_fast(acc[m][nt][2]),
                                         gelu_fast(acc[m][nt][3]));
                    uint32_t oa = sa  + (uint32_t)((nt ^ (ra & 7)) << 4);
                    uint32_t ob = sbt + (uint32_t)((nt ^ (rb & 7)) << 4);
                    *(uint32_t*)(smem + OFF_A + oa) = hA;
                    *(uint32_t*)(smem + OFF_A + ob) = hB;
                }
            }
            __syncthreads();
        } else {
            // ---- final: gelu*valid, reduce 32 edges -> per-node msum ----
            #pragma unroll
            for (int nt = 0; nt < 16; nt++) {
                float s0 = gelu_fast(acc[0][nt][0]) * vl4[0]
                         + gelu_fast(acc[0][nt][2]) * vl4[1]
                         + gelu_fast(acc[1][nt][0]) * vl4[2]
                         + gelu_fast(acc[1][nt][2]) * vl4[3];
                float s1 = gelu_fast(acc[0][nt][1]) * vl4[0]
                         + gelu_fast(acc[0][nt][3]) * vl4[1]
                         + gelu_fast(acc[1][nt][1]) * vl4[2]
                         + gelu_fast(acc[1][nt][3]) * vl4[3];
                #pragma unroll
                for (int sh = 4; sh < 32; sh <<= 1) {
                    s0 += __shfl_xor_sync(0xffffffffu, s0, sh);
                    s1 += __shfl_xor_sync(0xffffffffu, s1, sh);
                }
                if (l < 4) {
                    smf[(OFF_MSUM >> 2) + w * HH + 8 * nt + c2]     = s0;
                    smf[(OFF_MSUM >> 2) + w * HH + 8 * nt + c2 + 1] = s1;
                }
            }
            __syncthreads();
            #pragma unroll
            for (int g = 0; g < 4; g++) {
                float ms  = smf[(OFF_MSUM >> 2) + g * HH + tid];
                float upd = smf[(OFF_SELF >> 2) + g * HH + tid]
                          + ms * smf[(OFF_INV >> 2) + g] * smf[(OFF_NM >> 2) + g];
                g_upd[(size_t)(base_node + g) * HH + tid] = upd;
            }
        }
    }
}

// ---------------- graph norm: two-stage coalesced stats ----------------
// stage A: 128 blocks, each sums a contiguous 128-node chunk (coalesced rows)
__global__ __launch_bounds__(256)
void stats_a(const float* __restrict__ atom_mask)
{
    const int blk = blockIdx.x;
    const int b = blk >> 5, chunk = blk & 31;
    const int t = threadIdx.x;
    const int half = t >> 7, col = t & 127;
    const float* base = g_upd + ((size_t)(b * NN) + chunk * 128) * HH;

    // count valid nodes in chunk (threads 0..127, warps 0..3)
    float c = (t < 128) ? atom_mask[b * NN + chunk * 128 + t] : 0.0f;
    #pragma unroll
    for (int sh = 16; sh > 0; sh >>= 1)
        c += __shfl_xor_sync(0xffffffffu, c, sh);
    __shared__ float sc[8];
    if ((t & 31) == 0) sc[t >> 5] = c;

    float s = 0.0f, q = 0.0f;
    #pragma unroll 4
    for (int i = 0; i < 64; i++) {
        float v = base[(2 * i + half) * HH + col];
        s += v; q = fmaf(v, v, q);
    }
    __shared__ float ss[256], sq[256];
    ss[t] = s; sq[t] = q;
    __syncthreads();
    if (t < 128) {
        g_ps[(b * 32 + chunk) * HH + t] = ss[t] + ss[t + 128];
        g_pq[(b * 32 + chunk) * HH + t] = sq[t] + sq[t + 128];
    }
    if (t == 0)
        g_pc[b * 32 + chunk] = sc[0] + sc[1] + sc[2] + sc[3];
}

// stage B: one block combines 32 partials per (b,h)
__global__ __launch_bounds__(512)
void stats_b()
{
    const int t = threadIdx.x;          // t = b*128 + h
    const int b = t >> 7, h = t & 127;
    float s = 0.0f, q = 0.0f, c = 0.0f;
    #pragma unroll 8
    for (int ch = 0; ch < 32; ch++) {
        s += g_ps[(b * 32 + ch) * HH + h];
        q += g_pq[(b * 32 + ch) * HH + h];
        c += g_pc[b * 32 + ch];
    }
    if (c == 0.0f) c = 1.0f;
    float mean = s / c;
    float var = (q - 2.0f * mean * s + (float)NN * mean * mean) / c;
    g_mean[t] = mean;
    g_rstd[t] = rsqrtf(var + 1e-5f);
}

__global__ __launch_bounds__(256)
void norm_kernel(float* __restrict__ out,
                 const float* __restrict__ atom_mask,
                 const float* __restrict__ scale,
                 const float* __restrict__ shift)
{
    const int i = blockIdx.x * 256 + threadIdx.x;
    if (i >= NODES * HH) return;
    const int h  = i & (HH - 1);
    const int bn = i >> 7;
    const int b  = bn >> 12;
    const float v = g_upd[i];
    out[i] = ((v - g_mean[b * HH + h]) * g_rstd[b * HH + h] * scale[h] + shift[h])
             * atom_mask[bn];
}

__global__ __launch_bounds__(256)
void passthru_kernel(float* __restrict__ out,
                     const float* __restrict__ atom_mask,
                     const float* __restrict__ dist,
                     const int*   __restrict__ edge)
{
    const int M0 = NODES;
    const int M1 = NODES * KK;
    const int total = M0 + 2 * M1;
    const int i = blockIdx.x * 256 + threadIdx.x;
    if (i >= total) return;
    if (i < M0)            out[i] = atom_mask[i];
    else if (i < M0 + M1)  out[i] = dist[i - M0];
    else                   out[i] = (float)edge[i - M0 - M1];
}

extern "C" void kernel_launch(void* const* d_in, const int* in_sizes, int n_in,
                              void* d_out, int out_size)
{
    const float* atom_encode = (const float*)d_in[0];
    const float* atom_mask   = (const float*)d_in[1];
    const float* dist        = (const float*)d_in[2];
    const int*   edge_index  = (const int*)  d_in[3];
    const float* W0 = (const float*)d_in[4];
    const float* b0 = (const float*)d_in[5];
    const float* b1 = (const float*)d_in[7];
    const float* b2 = (const float*)d_in[9];
    const float* scale = (const float*)d_in[10];
    const float* shift = (const float*)d_in[11];
    float* out = (float*)d_out;

    cudaFuncSetAttribute(mpnn_tc, cudaFuncAttributeMaxDynamicSharedMemorySize,
                         SMEM_BYTES);
    cudaFuncSetAttribute(sbias_kernel, cudaFuncAttributeMaxDynamicSharedMemorySize,
                         SB_SMEM);

    prep_weights<<<(4 * HH * HH + 255) / 256, 256>>>(
        (const float*)d_in[4], (const float*)d_in[6], (const float*)d_in[8]);
    sbias_kernel<<<NODES / 128, 128, SB_SMEM>>>(atom_encode, atom_mask, b0);
    mpnn_tc<<<NODES / 4, 128, SMEM_BYTES>>>(atom_encode, atom_mask, dist,
                                            edge_index, W0, b1, b2);
    stats_a<<<BB * 32, 256>>>(atom_mask);
    stats_b<<<1, 512>>>();

    const int OUT0 = NODES * HH;
    norm_kernel<<<(OUT0 + 255) / 256, 256>>>(out, atom_mask, scale, shift);

    const int PT = NODES + 2 * NODES * KK;
    if (out_size >= OUT0 + PT) {
        passthru_kernel<<<(PT + 255) / 256, 256>>>(out + OUT0, atom_mask, dist,
                                                   edge_index);
    }
}